// round 10
// baseline (speedup 1.0000x reference)
#include <cuda_runtime.h>
#include <math.h>

// ---------------- problem constants ----------------
#define B_    4
#define C_    64
#define NPIX_ 16777216            // B*C*H*W
#define NT_   16384               // B * NPAT
#define TOK_  1024
#define SF_   2114
#define KSEL_ 1024
#define E_    128
#define SELSZ_ ((long)B_ * KSEL_ * TOK_)
#define QSZ_   (B_ * KSEL_ * E_)
#define ATTSZ_ ((long)B_ * 4 * KSEL_ * KSEL_)
#define NROWS_ (32 * 1024)        // (2 branches * 16 z) * 1024 rows

typedef unsigned long long ull;

// ---------------- device scratch (2x for batched branches) ----------------
__device__ float2 g_cA[NPIX_];
__device__ float  g_ampV[NPIX_];
__device__ float  g_ampI[NPIX_];
__device__ float  g_phV [NPIX_];
__device__ float  g_phI [NPIX_];
__device__ float  g_faMap[NPIX_];
__device__ float  g_fpMap[NPIX_];
__device__ float  g_spatial[NPIX_];
__device__ float  g_r1[NPIX_];
__device__ float  g_scoreArr[2 * NT_];
__device__ int    g_idxArr[2 * B_ * KSEL_];
__device__ float  g_selV[2 * SELSZ_];
__device__ float  g_selI[2 * SELSZ_];
__device__ float  g_qb[2 * QSZ_];
__device__ float  g_kb[2 * QSZ_];
__device__ float  g_vb[2 * QSZ_];
__device__ float  g_ob[2 * QSZ_];
__device__ float  g_att[2 * ATTSZ_];
__device__ float  g_fs[2 * SELSZ_];
__device__ float  g_gm[B_ * 2 * C_];
__device__ float  g_intentArr[B_ * 64];
__device__ float  g_t256r[256];
__device__ float  g_t256i[256];
__device__ float  g_pmax[NROWS_ * 16];
__device__ float  g_psum[NROWS_ * 16];
__device__ float  g_gmax[NROWS_];
__device__ float  g_gsum[NROWS_];

// ---------------- packed f32x2 helpers (sm_103a FFMA2) ----------------
__device__ __forceinline__ ull pk2(float lo, float hi) {
    ull r;
    asm("mov.b64 %0, {%1, %2};" : "=l"(r) : "f"(lo), "f"(hi));
    return r;
}
__device__ __forceinline__ void upk2(ull v, float& lo, float& hi) {
    asm("mov.b64 {%0, %1}, %2;" : "=f"(lo), "=f"(hi) : "l"(v));
}
#define FMA2_(d, a, b) asm("fma.rn.f32x2 %0, %1, %2, %0;" : "+l"(d) : "l"(a), "l"(b))

// ---------------- twiddles ----------------
__global__ void twiddle_init_kernel() {
    int k = threadIdx.x;
    double a = -2.0 * 3.14159265358979323846 * (double)k / 256.0;
    g_t256r[k] = (float)cos(a);
    g_t256i[k] = (float)sin(a);
}

// ---------------- 16-point register FFT ----------------
__device__ __forceinline__ void fft16_reg(float* xr, float* xi, float dsign) {
    #define SW16_(a,b) { float t=xr[a]; xr[a]=xr[b]; xr[b]=t; t=xi[a]; xi[a]=xi[b]; xi[b]=t; }
    SW16_(1,8) SW16_(2,4) SW16_(3,12) SW16_(5,10) SW16_(7,14) SW16_(11,13)
    #undef SW16_
    const float C16[8] = {1.f, 0.9238795325112867f, 0.7071067811865476f, 0.3826834323650898f,
                          0.f, -0.3826834323650898f, -0.7071067811865476f, -0.9238795325112867f};
    const float S16[8] = {0.f, 0.3826834323650898f, 0.7071067811865476f, 0.9238795325112867f,
                          1.f, 0.9238795325112867f, 0.7071067811865476f, 0.3826834323650898f};
    #pragma unroll
    for (int s = 1; s <= 4; s++) {
        const int half = 1 << (s - 1);
        #pragma unroll
        for (int j = 0; j < 8; j++) {
            const int grp = j >> (s - 1);
            const int pos = j & (half - 1);
            const int i = (grp << s) + pos;
            const int l = i + half;
            const int ti = pos << (4 - s);
            float wr = C16[ti];
            float wi = -dsign * S16[ti];
            float vr = xr[l] * wr - xi[l] * wi;
            float vi = xr[l] * wi + xi[l] * wr;
            float ur = xr[i], ui = xi[i];
            xr[i] = ur + vr; xi[i] = ui + vi;
            xr[l] = ur - vr; xi[l] = ui - vi;
        }
    }
}

// ---------------- 256-pt FFT pass ----------------
#define FFT_SM 4352
__global__ void fft_pass2_kernel(const float2* __restrict__ cin,
                                 const float* __restrict__ rin,
                                 const float* __restrict__ fa,
                                 const float* __restrict__ fp,
                                 float2* __restrict__ cout,
                                 float* __restrict__ amp,
                                 float* __restrict__ ph,
                                 float* __restrict__ rout,
                                 int colmode, int dir, float scale) {
    __shared__ float sre[FFT_SM];
    __shared__ float sim[FFT_SM];
    int tid = threadIdx.x;
    int tx = tid & 15, ty = tid >> 4;
    int u = colmode ? ty : tx;
    int s = colmode ? tx : ty;
    int line = blockIdx.x * 16 + s;
    int plane = line >> 8, l = line & 255;
    long base; int stride;
    if (colmode) { base = (long)plane * 65536 + l; stride = 256; }
    else         { base = (long)plane * 65536 + (long)l * 256; stride = 1; }
    float dsign = (dir > 0) ? 1.f : -1.f;

    float xr[16], xi[16];
    #pragma unroll
    for (int n2 = 0; n2 < 16; n2++) {
        long a = base + (long)(u + 16 * n2) * stride;
        if (rin)      { xr[n2] = rin[a]; xi[n2] = 0.f; }
        else if (fa)  { float am = fa[a]; float sn, cs; sincosf(fp[a], &sn, &cs);
                        xr[n2] = am * cs; xi[n2] = am * sn; }
        else          { float2 c = cin[a]; xr[n2] = c.x; xi[n2] = c.y; }
    }
    fft16_reg(xr, xi, dsign);
    #pragma unroll
    for (int k2 = 0; k2 < 16; k2++) {
        int m = u * k2;
        float wr = g_t256r[m];
        float wi = dsign * g_t256i[m];
        float a = xr[k2], b = xi[k2];
        xr[k2] = a * wr - b * wi;
        xi[k2] = a * wi + b * wr;
    }
    #pragma unroll
    for (int k2 = 0; k2 < 16; k2++) {
        int idx = colmode ? ((k2 * 16 + u) * 17 + s) : (s * 272 + k2 * 17 + u);
        sre[idx] = xr[k2]; sim[idx] = xi[k2];
    }
    __syncthreads();
    #pragma unroll
    for (int n1 = 0; n1 < 16; n1++) {
        int idx = colmode ? ((u * 16 + n1) * 17 + s) : (s * 272 + u * 17 + n1);
        xr[n1] = sre[idx]; xi[n1] = sim[idx];
    }
    fft16_reg(xr, xi, dsign);
    #pragma unroll
    for (int k1 = 0; k1 < 16; k1++) {
        long a = base + (long)(16 * k1 + u) * stride;
        float rr = xr[k1] * scale, ii = xi[k1] * scale;
        if (cout)      cout[a] = make_float2(rr, ii);
        else if (amp)  { amp[a] = sqrtf(rr * rr + ii * ii); ph[a] = atan2f(ii, rr); }
        else           rout[a] = rr;
    }
}

// ---------------- router ----------------
__global__ void gap_kernel(const float* __restrict__ vis, const float* __restrict__ ir,
                           float* __restrict__ gm) {
    __shared__ float red[256];
    int b = blockIdx.x >> 7;
    int ch = blockIdx.x & 127;
    const float* p = (ch < 64) ? (vis + (long)(b * 64 + ch) * 65536)
                               : (ir  + (long)(b * 64 + ch - 64) * 65536);
    float s = 0.f;
    for (int i = threadIdx.x; i < 65536; i += 256) s += p[i];
    red[threadIdx.x] = s;
    __syncthreads();
    for (int st = 128; st > 0; st >>= 1) {
        if (threadIdx.x < st) red[threadIdx.x] += red[threadIdx.x + st];
        __syncthreads();
    }
    if (threadIdx.x == 0) gm[blockIdx.x] = red[0] * (1.0f / 65536.0f);
}

__global__ void router_kernel(const float* __restrict__ gm, const float* __restrict__ Wr,
                              const float* __restrict__ br, const float* __restrict__ bank,
                              float* __restrict__ intent) {
    __shared__ float pf[4][64];
    __shared__ float lg[4][4];
    __shared__ float w[4][4];
    int t = threadIdx.x;
    for (int b = 0; b < 4; b++) {
        float s = br[t];
        for (int c = 0; c < 128; c++) s += gm[b * 128 + c] * Wr[c * 64 + t];
        pf[b][t] = s;
    }
    __syncthreads();
    if (t < 16) {
        int b = t >> 2, j = t & 3;
        float s = 0.f;
        for (int p = 0; p < 64; p++) s += pf[b][p] * bank[j * 64 + p];
        lg[b][j] = s;
    }
    __syncthreads();
    if (t < 4) {
        int b = t;
        float m = fmaxf(fmaxf(lg[b][0], lg[b][1]), fmaxf(lg[b][2], lg[b][3]));
        float e0 = expf(lg[b][0] - m), e1 = expf(lg[b][1] - m);
        float e2 = expf(lg[b][2] - m), e3 = expf(lg[b][3] - m);
        float s = e0 + e1 + e2 + e3;
        w[b][0] = e0 / s; w[b][1] = e1 / s; w[b][2] = e2 / s; w[b][3] = e3 / s;
    }
    __syncthreads();
    for (int b = 0; b < 4; b++) {
        float s = 0.f;
        for (int j = 0; j < 4; j++) s += w[b][j] * bank[j * 64 + t];
        intent[b * 64 + t] = s;
    }
}

// ---------------- fused score net, branch-batched, FMA2 inner ----------------
__global__ void __launch_bounds__(256) score_fused_kernel(
        const float* __restrict__ ampV, const float* __restrict__ ampI,
        const float* __restrict__ phV, const float* __restrict__ phI,
        const float* __restrict__ intent,
        const float* __restrict__ aW1, const float* __restrict__ ab1,
        const float* __restrict__ aW2, const float* __restrict__ ab2,
        const float* __restrict__ pW1, const float* __restrict__ pb1,
        const float* __restrict__ pW2, const float* __restrict__ pb2,
        float* __restrict__ score) {
    const int BM = 64, BK = 16;
    __shared__ float As[BK][68];
    __shared__ float Bs[BK][132];
    __shared__ float red[64 * 16];
    int brx = blockIdx.y;
    const float* mapV = brx ? phV : ampV;
    const float* mapI = brx ? phI : ampI;
    const float* W1 = brx ? pW1 : aW1;
    const float* b1 = brx ? pb1 : ab1;
    const float* W2 = brx ? pW2 : aW2;
    const float* b2 = brx ? pb2 : ab2;

    int tid = threadIdx.x;
    int row0 = blockIdx.x * BM;
    int ty = tid >> 4, tx = tid & 15;

    ull acc2[4][4];
    #pragma unroll
    for (int i = 0; i < 4; i++)
        #pragma unroll
        for (int jp = 0; jp < 4; jp++) acc2[i][jp] = 0ull;

    for (int k0 = 0; k0 < SF_; k0 += BK) {
        #pragma unroll
        for (int lq = 0; lq < 4; lq++) {
            int e = tid + lq * 256;
            int r = e >> 4, c = e & 15;
            int col = k0 + c;
            int tok = row0 + r;
            int b = tok >> 12, n = tok & 4095;
            float v = 0.f;
            if (col < 2048) {
                int t = col & 1023;
                int ch = t >> 4, py = (t >> 2) & 3, px = t & 3;
                int hy = n >> 6, wx = n & 63;
                long m = (((long)(b * 64 + ch) * 256) + hy * 4 + py) * 256 + wx * 4 + px;
                v = (col < 1024) ? mapV[m] : mapI[m];
            } else if (col < SF_) {
                if (col == 2048)      v = (float)(n >> 6) * (1.0f / 63.0f);
                else if (col == 2049) v = (float)(n & 63) * (1.0f / 63.0f);
                else                  v = intent[b * 64 + (col - 2050)];
            }
            As[c][r] = v;
        }
        #pragma unroll
        for (int lq = 0; lq < 8; lq++) {
            int e = tid + lq * 256;
            int r = e >> 7, c = e & 127;
            Bs[r][c] = (k0 + r < SF_) ? W1[(long)(k0 + r) * 128 + c] : 0.f;
        }
        __syncthreads();
        #pragma unroll
        for (int kk = 0; kk < BK; kk++) {
            float4 av = *(const float4*)&As[kk][ty * 4];
            ull a2[4] = {pk2(av.x, av.x), pk2(av.y, av.y), pk2(av.z, av.z), pk2(av.w, av.w)};
            const ull* bp = (const ull*)&Bs[kk][tx * 8];
            ull b2v[4] = {bp[0], bp[1], bp[2], bp[3]};
            #pragma unroll
            for (int i = 0; i < 4; i++)
                #pragma unroll
                for (int jp = 0; jp < 4; jp++)
                    FMA2_(acc2[i][jp], a2[i], b2v[jp]);
        }
        __syncthreads();
    }

    float w2[8], bs[8];
    #pragma unroll
    for (int j = 0; j < 8; j++) { w2[j] = W2[tx * 8 + j]; bs[j] = b1[tx * 8 + j]; }
    #pragma unroll
    for (int i = 0; i < 4; i++) {
        float p = 0.f;
        #pragma unroll
        for (int jp = 0; jp < 4; jp++) {
            float c0, c1;
            upk2(acc2[i][jp], c0, c1);
            float h0 = fmaxf(c0 + bs[2 * jp], 0.f);
            float h1 = fmaxf(c1 + bs[2 * jp + 1], 0.f);
            p += h0 * w2[2 * jp] + h1 * w2[2 * jp + 1];
        }
        red[(ty * 4 + i) * 16 + tx] = p;
    }
    __syncthreads();
    if (tid < 64) {
        float s = 0.f;
        #pragma unroll
        for (int q = 0; q < 16; q++) s += red[tid * 16 + q];
        score[brx * NT_ + row0 + tid] = s + b2[0];
    }
}

// ---------------- batched 64x128 FMA2 GEMM: C = A@W (+residual) ----------------
struct GB { const float* A; const float* W; float* C; const float* R; };
struct GB8 { GB g[8]; };

__global__ void __launch_bounds__(256) gemm_batched_kernel(GB8 gb, int M, int N, int K) {
    const int BK = 16;
    __shared__ float As[BK][68];
    __shared__ float Bs[BK][132];
    GB p = gb.g[blockIdx.z];
    int tid = threadIdx.x;
    int row0 = blockIdx.y * 64, col0 = blockIdx.x * 128;
    int ty = tid >> 4, tx = tid & 15;

    ull acc2[4][4];
    #pragma unroll
    for (int i = 0; i < 4; i++)
        #pragma unroll
        for (int jp = 0; jp < 4; jp++) acc2[i][jp] = 0ull;

    for (int k0 = 0; k0 < K; k0 += BK) {
        #pragma unroll
        for (int lq = 0; lq < 4; lq++) {
            int e = tid + lq * 256;
            int r = e >> 4, c = e & 15;
            As[c][r] = p.A[(long)(row0 + r) * K + (k0 + c)];
        }
        #pragma unroll
        for (int lq = 0; lq < 8; lq++) {
            int e = tid + lq * 256;
            int r = e >> 7, c = e & 127;
            Bs[r][c] = p.W[(long)(k0 + r) * N + (col0 + c)];
        }
        __syncthreads();
        #pragma unroll
        for (int kk = 0; kk < BK; kk++) {
            float4 av = *(const float4*)&As[kk][ty * 4];
            ull a2[4] = {pk2(av.x, av.x), pk2(av.y, av.y), pk2(av.z, av.z), pk2(av.w, av.w)};
            const ull* bp = (const ull*)&Bs[kk][tx * 8];
            ull b2v[4] = {bp[0], bp[1], bp[2], bp[3]};
            #pragma unroll
            for (int i = 0; i < 4; i++)
                #pragma unroll
                for (int jp = 0; jp < 4; jp++)
                    FMA2_(acc2[i][jp], a2[i], b2v[jp]);
        }
        __syncthreads();
    }
    #pragma unroll
    for (int i = 0; i < 4; i++) {
        long r = row0 + ty * 4 + i;
        #pragma unroll
        for (int jp = 0; jp < 4; jp++) {
            float v0, v1;
            upk2(acc2[i][jp], v0, v1);
            long c0 = col0 + tx * 8 + 2 * jp;
            if (p.R) {
                v0 += p.R[r * N + c0];
                v1 += p.R[r * N + c0 + 1];
            }
            p.C[r * N + c0]     = v0;
            p.C[r * N + c0 + 1] = v1;
        }
    }
}

// ---------------- top-k via bitonic sort (branch-batched) ----------------
__global__ void __launch_bounds__(1024) topk_kernel(const float* __restrict__ score,
                                                    int* __restrict__ idxo) {
    __shared__ float key[4096];
    __shared__ int val[4096];
    int b4 = blockIdx.x;
    int brx = b4 >> 2, b = b4 & 3;
    int t = threadIdx.x;
    const float* sp = score + brx * NT_ + b * 4096;
    for (int i = t; i < 4096; i += 1024) { key[i] = sp[i]; val[i] = i; }
    __syncthreads();
    for (int k = 2; k <= 4096; k <<= 1) {
        for (int j = k >> 1; j > 0; j >>= 1) {
            for (int i = t; i < 4096; i += 1024) {
                int ixj = i ^ j;
                if (ixj > i) {
                    bool desc = ((i & k) == 0);
                    float a = key[i], c = key[ixj];
                    bool sw = desc ? (a < c) : (a > c);
                    if (sw) {
                        key[i] = c; key[ixj] = a;
                        int tv = val[i]; val[i] = val[ixj]; val[ixj] = tv;
                    }
                }
            }
            __syncthreads();
        }
    }
    if (t < 1024) idxo[b4 * 1024 + t] = val[t];
}

// ---------------- gather / scatter (branch-batched) ----------------
__device__ __forceinline__ long patch_pixel(int b, int n, int t) {
    int hy = n >> 6, wx = n & 63;
    int c = t >> 4, py = (t >> 2) & 3, px = t & 3;
    return (((long)(b * 64 + c) * 256) + hy * 4 + py) * 256 + wx * 4 + px;
}

__global__ void gather_kernel(const float* __restrict__ ampV, const float* __restrict__ ampI,
                              const float* __restrict__ phV, const float* __restrict__ phI,
                              const int* __restrict__ idx,
                              float* __restrict__ selV, float* __restrict__ selI) {
    int brx = blockIdx.y;
    const float* mapV = brx ? phV : ampV;
    const float* mapI = brx ? phI : ampI;
    long gid = (long)blockIdx.x * 256 + threadIdx.x;
    int bi = (int)(gid >> 10);
    int t = (int)(gid & 1023);
    int b = bi >> 10;
    int n = idx[brx * 4096 + bi];
    long m = patch_pixel(b, n, t);
    long off = (long)brx * SELSZ_;
    selV[off + gid] = mapV[m];
    selI[off + gid] = mapI[m];
}

__global__ void scatter_kernel(const float* __restrict__ fs, const int* __restrict__ idx,
                               float* __restrict__ faMap, float* __restrict__ fpMap) {
    int brx = blockIdx.y;
    float* outMap = brx ? fpMap : faMap;
    long gid = (long)blockIdx.x * 256 + threadIdx.x;
    int bi = (int)(gid >> 10);
    int t = (int)(gid & 1023);
    int b = bi >> 10;
    int n = idx[brx * 4096 + bi];
    long m = patch_pixel(b, n, t);
    outMap[m] = fs[(long)brx * SELSZ_ + gid];
}

// ---------------- attention: scores + split-softmax partials ----------------
__global__ void __launch_bounds__(256) attn_scores_kernel(
        const float* __restrict__ Q, const float* __restrict__ Kt,
        float* __restrict__ S, float* __restrict__ pmax, float* __restrict__ psum) {
    __shared__ __align__(16) float Qs[64][33];
    __shared__ __align__(16) float KsT[32][66];   // [d][j], even stride for ull loads
    __shared__ float rmaxS[64][17];
    __shared__ float rsumS[64][17];
    int z = blockIdx.z;                 // 0..31 = br*16 + (b*4+h)
    int brx = z >> 4, zz = z & 15;
    int b = zz >> 2, h = zz & 3;
    const float* Qp = Q + (long)brx * QSZ_ + (long)b * 1024 * 128 + h * 32;
    const float* Kp = Kt + (long)brx * QSZ_ + (long)b * 1024 * 128 + h * 32;
    int i0 = blockIdx.y * 64, j0 = blockIdx.x * 64;
    int tid = threadIdx.x;
    #pragma unroll
    for (int l = 0; l < 8; l++) {
        int e = tid + l * 256;
        int r = e >> 5, c = e & 31;
        Qs[r][c] = Qp[(long)(i0 + r) * 128 + c];
        KsT[c][r] = Kp[(long)(j0 + r) * 128 + c];
    }
    __syncthreads();
    int ty = tid >> 4, tx = tid & 15;
    ull acc2[4][2];
    #pragma unroll
    for (int i = 0; i < 4; i++) { acc2[i][0] = 0ull; acc2[i][1] = 0ull; }
    #pragma unroll
    for (int d = 0; d < 32; d++) {
        const ull* bp = (const ull*)&KsT[d][tx * 4];
        ull b0 = bp[0], b1 = bp[1];
        #pragma unroll
        for (int i = 0; i < 4; i++) {
            float a = Qs[ty * 4 + i][d];
            ull a2 = pk2(a, a);
            FMA2_(acc2[i][0], a2, b0);
            FMA2_(acc2[i][1], a2, b1);
        }
    }
    const float scale = 0.17677669529663687f;
    float sc[4][4];
    #pragma unroll
    for (int i = 0; i < 4; i++) {
        upk2(acc2[i][0], sc[i][0], sc[i][1]);
        upk2(acc2[i][1], sc[i][2], sc[i][3]);
        float m = -3.4e38f;
        #pragma unroll
        for (int j = 0; j < 4; j++) { sc[i][j] *= scale; m = fmaxf(m, sc[i][j]); }
        // vectorized store of the 4 contiguous cols
        *(float4*)&S[((long)z * 1024 + i0 + ty * 4 + i) * 1024 + j0 + tx * 4] =
            make_float4(sc[i][0], sc[i][1], sc[i][2], sc[i][3]);
        rmaxS[ty * 4 + i][tx] = m;
    }
    __syncthreads();
    if (tid < 64) {
        float m = rmaxS[tid][0];
        #pragma unroll
        for (int q = 1; q < 16; q++) m = fmaxf(m, rmaxS[tid][q]);
        rmaxS[tid][16] = m;
    }
    __syncthreads();
    #pragma unroll
    for (int i = 0; i < 4; i++) {
        float m = rmaxS[ty * 4 + i][16];
        float p = 0.f;
        #pragma unroll
        for (int j = 0; j < 4; j++) p += __expf(sc[i][j] - m);
        rsumS[ty * 4 + i][tx] = p;
    }
    __syncthreads();
    if (tid < 64) {
        float s = 0.f;
        #pragma unroll
        for (int q = 0; q < 16; q++) s += rsumS[tid][q];
        long ridx = ((long)z * 1024 + i0 + tid) * 16 + blockIdx.x;
        pmax[ridx] = rmaxS[tid][16];
        psum[ridx] = s;
    }
}

// ---------------- attention: combine split-softmax partials per row ----------------
__global__ void attn_reduce_kernel(const float* __restrict__ pmax,
                                   const float* __restrict__ psum,
                                   float* __restrict__ gmax, float* __restrict__ gsum) {
    int r = blockIdx.x * 256 + threadIdx.x;     // 0..32767
    const float* pm = pmax + (long)r * 16;
    const float* ps = psum + (long)r * 16;
    float m = pm[0];
    #pragma unroll
    for (int q = 1; q < 16; q++) m = fmaxf(m, pm[q]);
    float s = 0.f;
    #pragma unroll
    for (int q = 0; q < 16; q++) s += ps[q] * __expf(pm[q] - m);
    gmax[r] = m;
    gsum[r] = s;
}

// ---------------- attention: apply (exp on load, FMA2, normalize at end) ----------------
__global__ void __launch_bounds__(256) attn_apply_kernel(
        const float* __restrict__ S, const float* __restrict__ V,
        const float* __restrict__ gmax, const float* __restrict__ gsum,
        float* __restrict__ O) {
    __shared__ __align__(16) float Ps[64][66];
    __shared__ __align__(16) float Vs[64][34];
    __shared__ float gmr[64], gsr[64];
    int z = blockIdx.y;                 // 0..31
    int brx = z >> 4, zz = z & 15;
    int b = zz >> 2, h = zz & 3;
    int i0 = blockIdx.x * 64;
    int tid = threadIdx.x;
    int ty = tid >> 4, tx = tid & 15;
    const float* Vp = V + (long)brx * QSZ_;
    float* Op = O + (long)brx * QSZ_;
    if (tid < 64) {
        gmr[tid] = gmax[(long)z * 1024 + i0 + tid];
        gsr[tid] = gsum[(long)z * 1024 + i0 + tid];
    }
    __syncthreads();
    ull acc2[4];
    #pragma unroll
    for (int i = 0; i < 4; i++) acc2[i] = 0ull;
    for (int j0 = 0; j0 < 1024; j0 += 64) {
        #pragma unroll
        for (int l = 0; l < 16; l++) {
            int e = tid + l * 256;
            int r = e >> 6, c = e & 63;
            float s = S[((long)z * 1024 + i0 + r) * 1024 + j0 + c];
            Ps[r][c] = __expf(s - gmr[r]);
        }
        #pragma unroll
        for (int l = 0; l < 8; l++) {
            int e = tid + l * 256;
            int r = e >> 5, c = e & 31;
            Vs[r][c] = Vp[(long)(b * 1024 + j0 + r) * 128 + h * 32 + c];
        }
        __syncthreads();
        #pragma unroll
        for (int kk = 0; kk < 64; kk++) {
            ull v2 = *(const ull*)&Vs[kk][tx * 2];
            #pragma unroll
            for (int i = 0; i < 4; i++) {
                float a = Ps[ty * 4 + i][kk];
                FMA2_(acc2[i], pk2(a, a), v2);
            }
        }
        __syncthreads();
    }
    #pragma unroll
    for (int i = 0; i < 4; i++) {
        float v0, v1;
        upk2(acc2[i], v0, v1);
        float inv = 1.0f / gsr[ty * 4 + i];
        long obase = (long)(b * 1024 + i0 + ty * 4 + i) * 128 + h * 32 + tx * 2;
        Op[obase]     = v0 * inv;
        Op[obase + 1] = v1 * inv;
    }
}

// ---------------- elementwise avg (branch-batched) ----------------
__global__ void avg_kernel(const float* __restrict__ ampV, const float* __restrict__ ampI,
                           float* __restrict__ faMap,
                           const float* __restrict__ phV, const float* __restrict__ phI,
                           float* __restrict__ fpMap) {
    int brx = blockIdx.y;
    long i = (long)blockIdx.x * 256 + threadIdx.x;
    if (brx == 0) faMap[i] = 0.5f * (ampV[i] + ampI[i]);
    else          fpMap[i] = 0.5f * (phV[i] + phI[i]);
}

// ---------------- 3x3 SAME conv: 16x16 tile, 64 co/block, channel-pair FMA2 ----------------
__global__ void __launch_bounds__(256) conv3_kernel(
        const float* __restrict__ in, const float* __restrict__ wgt,
        const float* __restrict__ bias, float* __restrict__ out,
        const float* __restrict__ resA, const float* __restrict__ resB,
        int relu) {
    __shared__ float sIn[18][18];
    __shared__ float2 sW2[32][9];
    int bz = blockIdx.z;
    int x0 = blockIdx.x * 16, y0 = blockIdx.y * 16;
    int tx = threadIdx.x & 15, ty = threadIdx.x >> 4;
    int tid = threadIdx.x;
    int x = x0 + tx, y = y0 + ty;

    ull acc[32];
    #pragma unroll
    for (int p = 0; p < 32; p++) acc[p] = 0ull;

    for (int ci = 0; ci < 64; ci++) {
        const float* ip = in + (long)(bz * 64 + ci) * 65536;
        for (int e = tid; e < 324; e += 256) {
            int ry = e / 18, rx = e % 18;
            int gy = y0 + ry - 1, gx = x0 + rx - 1;
            sIn[ry][rx] = (gy >= 0 && gy < 256 && gx >= 0 && gx < 256) ? ip[gy * 256 + gx] : 0.f;
        }
        for (int e = tid; e < 288; e += 256) {
            int p = e / 9, k = e % 9;
            sW2[p][k] = make_float2(wgt[((long)(2 * p) * 64 + ci) * 9 + k],
                                    wgt[((long)(2 * p + 1) * 64 + ci) * 9 + k]);
        }
        __syncthreads();
        ull vp[9];
        #pragma unroll
        for (int ky = 0; ky < 3; ky++)
            #pragma unroll
            for (int kx = 0; kx < 3; kx++) {
                float v = sIn[ty + ky][tx + kx];
                vp[ky * 3 + kx] = pk2(v, v);
            }
        #pragma unroll
        for (int p = 0; p < 32; p++) {
            #pragma unroll
            for (int k = 0; k < 9; k++) {
                ull w2 = *(const ull*)&sW2[p][k];
                FMA2_(acc[p], vp[k], w2);
            }
        }
        __syncthreads();
    }
    #pragma unroll
    for (int p = 0; p < 32; p++) {
        float v0, v1;
        upk2(acc[p], v0, v1);
        int co0 = 2 * p, co1 = 2 * p + 1;
        long o0 = ((long)(bz * 64 + co0) * 256 + y) * 256 + x;
        long o1 = ((long)(bz * 64 + co1) * 256 + y) * 256 + x;
        v0 += bias[co0];
        v1 += bias[co1];
        if (relu) { v0 = fmaxf(v0, 0.f); v1 = fmaxf(v1, 0.f); }
        if (resA) {
            v0 += 0.5f * (resA[o0] + resB[o0]);
            v1 += 0.5f * (resA[o1] + resB[o1]);
        }
        out[o0] = v0;
        out[o1] = v1;
    }
}

extern "C" void kernel_launch(void* const* d_in, const int* in_sizes, int n_in,
                              void* d_out, int out_size) {
    const float* vis  = (const float*)d_in[0];
    const float* ir   = (const float*)d_in[1];
    const float* bank = (const float*)d_in[2];
    const float* Wr   = (const float*)d_in[3];
    const float* br   = (const float*)d_in[4];
    const float* aW1  = (const float*)d_in[5];
    const float* ab1  = (const float*)d_in[6];
    const float* aW2  = (const float*)d_in[7];
    const float* ab2  = (const float*)d_in[8];
    const float* aWq  = (const float*)d_in[9];
    const float* aWk  = (const float*)d_in[10];
    const float* aWv  = (const float*)d_in[11];
    const float* aWo  = (const float*)d_in[12];
    const float* pW1  = (const float*)d_in[13];
    const float* pb1  = (const float*)d_in[14];
    const float* pW2  = (const float*)d_in[15];
    const float* pb2  = (const float*)d_in[16];
    const float* pWq  = (const float*)d_in[17];
    const float* pWk  = (const float*)d_in[18];
    const float* pWv  = (const float*)d_in[19];
    const float* pWo  = (const float*)d_in[20];
    const float* c1w  = (const float*)d_in[21];
    const float* c1b  = (const float*)d_in[22];
    const float* c2w  = (const float*)d_in[23];
    const float* c2b  = (const float*)d_in[24];
    float* out = (float*)d_out;

    float2* cA;
    float *ampV, *ampI, *phV, *phI, *faMap, *fpMap, *spatial, *r1;
    float *score, *selV, *selI, *q, *k, *v, *o, *att, *fs, *gm, *intent;
    float *pmax, *psum, *gmaxp, *gsump;
    int* idxp;
    cudaGetSymbolAddress((void**)&cA, g_cA);
    cudaGetSymbolAddress((void**)&ampV, g_ampV);
    cudaGetSymbolAddress((void**)&ampI, g_ampI);
    cudaGetSymbolAddress((void**)&phV, g_phV);
    cudaGetSymbolAddress((void**)&phI, g_phI);
    cudaGetSymbolAddress((void**)&faMap, g_faMap);
    cudaGetSymbolAddress((void**)&fpMap, g_fpMap);
    cudaGetSymbolAddress((void**)&spatial, g_spatial);
    cudaGetSymbolAddress((void**)&r1, g_r1);
    cudaGetSymbolAddress((void**)&score, g_scoreArr);
    cudaGetSymbolAddress((void**)&idxp, g_idxArr);
    cudaGetSymbolAddress((void**)&selV, g_selV);
    cudaGetSymbolAddress((void**)&selI, g_selI);
    cudaGetSymbolAddress((void**)&q, g_qb);
    cudaGetSymbolAddress((void**)&k, g_kb);
    cudaGetSymbolAddress((void**)&v, g_vb);
    cudaGetSymbolAddress((void**)&o, g_ob);
    cudaGetSymbolAddress((void**)&att, g_att);
    cudaGetSymbolAddress((void**)&fs, g_fs);
    cudaGetSymbolAddress((void**)&gm, g_gm);
    cudaGetSymbolAddress((void**)&intent, g_intentArr);
    cudaGetSymbolAddress((void**)&pmax, g_pmax);
    cudaGetSymbolAddress((void**)&psum, g_psum);
    cudaGetSymbolAddress((void**)&gmaxp, g_gmax);
    cudaGetSymbolAddress((void**)&gsump, g_gsum);

    twiddle_init_kernel<<<1, 256>>>();
    gap_kernel<<<512, 256>>>(vis, ir, gm);
    router_kernel<<<1, 64>>>(gm, Wr, br, bank, intent);

    const int FB = 4096;
    fft_pass2_kernel<<<FB, 256>>>(nullptr, vis, nullptr, nullptr, cA, nullptr, nullptr, nullptr, 0, +1, 1.f);
    fft_pass2_kernel<<<FB, 256>>>(cA, nullptr, nullptr, nullptr, nullptr, ampV, phV, nullptr, 1, +1, 1.f);
    fft_pass2_kernel<<<FB, 256>>>(nullptr, ir, nullptr, nullptr, cA, nullptr, nullptr, nullptr, 0, +1, 1.f);
    fft_pass2_kernel<<<FB, 256>>>(cA, nullptr, nullptr, nullptr, nullptr, ampI, phI, nullptr, 1, +1, 1.f);

    // ----- batched branch pipeline -----
    score_fused_kernel<<<dim3(256, 2), 256>>>(ampV, ampI, phV, phI, intent,
                                              aW1, ab1, aW2, ab2, pW1, pb1, pW2, pb2, score);
    topk_kernel<<<8, 1024>>>(score, idxp);
    gather_kernel<<<dim3(16384, 2), 256>>>(ampV, ampI, phV, phI, idxp, selV, selI);

    GB8 qkv;
    qkv.g[0] = { selV,          aWq, q,          nullptr };
    qkv.g[1] = { selI,          aWk, k,          nullptr };
    qkv.g[2] = { selI,          aWv, v,          nullptr };
    qkv.g[3] = { selV + SELSZ_, pWq, q + QSZ_,   nullptr };
    qkv.g[4] = { selI + SELSZ_, pWk, k + QSZ_,   nullptr };
    qkv.g[5] = { selI + SELSZ_, pWv, v + QSZ_,   nullptr };
    qkv.g[6] = { nullptr, nullptr, nullptr, nullptr };
    qkv.g[7] = { nullptr, nullptr, nullptr, nullptr };
    gemm_batched_kernel<<<dim3(1, 64, 6), 256>>>(qkv, 4096, 128, 1024);

    attn_scores_kernel<<<dim3(16, 16, 32), 256>>>(q, k, att, pmax, psum);
    attn_reduce_kernel<<<128, 256>>>(pmax, psum, gmaxp, gsump);
    attn_apply_kernel<<<dim3(16, 32), 256>>>(att, v, gmaxp, gsump, o);

    GB8 wo;
    wo.g[0] = { o,        aWo, fs,          selV };
    wo.g[1] = { o + QSZ_, pWo, fs + SELSZ_, selV + SELSZ_ };
    for (int z = 2; z < 8; z++) wo.g[z] = { nullptr, nullptr, nullptr, nullptr };
    gemm_batched_kernel<<<dim3(8, 64, 2), 256>>>(wo, 4096, 1024, 128);

    avg_kernel<<<dim3(65536, 2), 256>>>(ampV, ampI, faMap, phV, phI, fpMap);
    scatter_kernel<<<dim3(16384, 2), 256>>>(fs, idxp, faMap, fpMap);

    fft_pass2_kernel<<<FB, 256>>>(nullptr, nullptr, faMap, fpMap, cA, nullptr, nullptr, nullptr, 0, -1, 1.f);
    fft_pass2_kernel<<<FB, 256>>>(cA, nullptr, nullptr, nullptr, nullptr, nullptr, nullptr, spatial, 1, -1, 1.0f / 65536.0f);

    conv3_kernel<<<dim3(16, 16, 4), 256>>>(spatial, c1w, c1b, r1, nullptr, nullptr, 1);
    conv3_kernel<<<dim3(16, 16, 4), 256>>>(r1, c2w, c2b, out, vis, ir, 0);

    (void)in_sizes; (void)n_in; (void)out_size;
}

// round 11
// speedup vs baseline: 1.0001x; 1.0001x over previous
#include <cuda_runtime.h>
#include <math.h>

// ---------------- problem constants ----------------
#define B_    4
#define C_    64
#define NPIX_ 16777216            // B*C*H*W
#define NT_   16384               // B * NPAT
#define TOK_  1024
#define SF_   2114
#define KSEL_ 1024
#define E_    128
#define SELSZ_ ((long)B_ * KSEL_ * TOK_)
#define QSZ_   (B_ * KSEL_ * E_)
#define ATTSZ_ ((long)B_ * 4 * KSEL_ * KSEL_)
#define NROWS_ (32 * 1024)        // (2 branches * 16 z) * 1024 rows

typedef unsigned long long ull;

// ---------------- device scratch (2x for batched branches) ----------------
__device__ float2 g_cA[NPIX_];
__device__ float  g_ampV[NPIX_];
__device__ float  g_ampI[NPIX_];
__device__ float  g_phV [NPIX_];
__device__ float  g_phI [NPIX_];
__device__ float  g_faMap[NPIX_];
__device__ float  g_fpMap[NPIX_];
__device__ float  g_spatial[NPIX_];
__device__ float  g_r1[NPIX_];
__device__ float  g_scoreArr[2 * NT_];
__device__ int    g_idxArr[2 * B_ * KSEL_];
__device__ float  g_selV[2 * SELSZ_];
__device__ float  g_selI[2 * SELSZ_];
__device__ float  g_qb[2 * QSZ_];
__device__ float  g_kb[2 * QSZ_];
__device__ float  g_vb[2 * QSZ_];
__device__ float  g_ob[2 * QSZ_];
__device__ float  g_att[2 * ATTSZ_];
__device__ float  g_fs[2 * SELSZ_];
__device__ float  g_gm[B_ * 2 * C_];
__device__ float  g_intentArr[B_ * 64];
__device__ float  g_t256r[256];
__device__ float  g_t256i[256];
__device__ float  g_pmax[NROWS_ * 16];
__device__ float  g_psum[NROWS_ * 16];
__device__ float  g_gmax[NROWS_];
__device__ float  g_gsum[NROWS_];

// ---------------- packed f32x2 helpers (sm_103a FFMA2) ----------------
__device__ __forceinline__ ull pk2(float lo, float hi) {
    ull r;
    asm("mov.b64 %0, {%1, %2};" : "=l"(r) : "f"(lo), "f"(hi));
    return r;
}
__device__ __forceinline__ void upk2(ull v, float& lo, float& hi) {
    asm("mov.b64 {%0, %1}, %2;" : "=f"(lo), "=f"(hi) : "l"(v));
}
#define FMA2_(d, a, b) asm("fma.rn.f32x2 %0, %1, %2, %0;" : "+l"(d) : "l"(a), "l"(b))

// ---------------- twiddles ----------------
__global__ void twiddle_init_kernel() {
    int k = threadIdx.x;
    double a = -2.0 * 3.14159265358979323846 * (double)k / 256.0;
    g_t256r[k] = (float)cos(a);
    g_t256i[k] = (float)sin(a);
}

// ---------------- 16-point register FFT ----------------
__device__ __forceinline__ void fft16_reg(float* xr, float* xi, float dsign) {
    #define SW16_(a,b) { float t=xr[a]; xr[a]=xr[b]; xr[b]=t; t=xi[a]; xi[a]=xi[b]; xi[b]=t; }
    SW16_(1,8) SW16_(2,4) SW16_(3,12) SW16_(5,10) SW16_(7,14) SW16_(11,13)
    #undef SW16_
    const float C16[8] = {1.f, 0.9238795325112867f, 0.7071067811865476f, 0.3826834323650898f,
                          0.f, -0.3826834323650898f, -0.7071067811865476f, -0.9238795325112867f};
    const float S16[8] = {0.f, 0.3826834323650898f, 0.7071067811865476f, 0.9238795325112867f,
                          1.f, 0.9238795325112867f, 0.7071067811865476f, 0.3826834323650898f};
    #pragma unroll
    for (int s = 1; s <= 4; s++) {
        const int half = 1 << (s - 1);
        #pragma unroll
        for (int j = 0; j < 8; j++) {
            const int grp = j >> (s - 1);
            const int pos = j & (half - 1);
            const int i = (grp << s) + pos;
            const int l = i + half;
            const int ti = pos << (4 - s);
            float wr = C16[ti];
            float wi = -dsign * S16[ti];
            float vr = xr[l] * wr - xi[l] * wi;
            float vi = xr[l] * wi + xi[l] * wr;
            float ur = xr[i], ui = xi[i];
            xr[i] = ur + vr; xi[i] = ui + vi;
            xr[l] = ur - vr; xi[l] = ui - vi;
        }
    }
}

// ---------------- 256-pt FFT pass ----------------
#define FFT_SM 4352
__global__ void fft_pass2_kernel(const float2* __restrict__ cin,
                                 const float* __restrict__ rin,
                                 const float* __restrict__ fa,
                                 const float* __restrict__ fp,
                                 float2* __restrict__ cout,
                                 float* __restrict__ amp,
                                 float* __restrict__ ph,
                                 float* __restrict__ rout,
                                 int colmode, int dir, float scale) {
    __shared__ float sre[FFT_SM];
    __shared__ float sim[FFT_SM];
    int tid = threadIdx.x;
    int tx = tid & 15, ty = tid >> 4;
    int u = colmode ? ty : tx;
    int s = colmode ? tx : ty;
    int line = blockIdx.x * 16 + s;
    int plane = line >> 8, l = line & 255;
    long base; int stride;
    if (colmode) { base = (long)plane * 65536 + l; stride = 256; }
    else         { base = (long)plane * 65536 + (long)l * 256; stride = 1; }
    float dsign = (dir > 0) ? 1.f : -1.f;

    float xr[16], xi[16];
    #pragma unroll
    for (int n2 = 0; n2 < 16; n2++) {
        long a = base + (long)(u + 16 * n2) * stride;
        if (rin)      { xr[n2] = rin[a]; xi[n2] = 0.f; }
        else if (fa)  { float am = fa[a]; float sn, cs; sincosf(fp[a], &sn, &cs);
                        xr[n2] = am * cs; xi[n2] = am * sn; }
        else          { float2 c = cin[a]; xr[n2] = c.x; xi[n2] = c.y; }
    }
    fft16_reg(xr, xi, dsign);
    #pragma unroll
    for (int k2 = 0; k2 < 16; k2++) {
        int m = u * k2;
        float wr = g_t256r[m];
        float wi = dsign * g_t256i[m];
        float a = xr[k2], b = xi[k2];
        xr[k2] = a * wr - b * wi;
        xi[k2] = a * wi + b * wr;
    }
    #pragma unroll
    for (int k2 = 0; k2 < 16; k2++) {
        int idx = colmode ? ((k2 * 16 + u) * 17 + s) : (s * 272 + k2 * 17 + u);
        sre[idx] = xr[k2]; sim[idx] = xi[k2];
    }
    __syncthreads();
    #pragma unroll
    for (int n1 = 0; n1 < 16; n1++) {
        int idx = colmode ? ((u * 16 + n1) * 17 + s) : (s * 272 + u * 17 + n1);
        xr[n1] = sre[idx]; xi[n1] = sim[idx];
    }
    fft16_reg(xr, xi, dsign);
    #pragma unroll
    for (int k1 = 0; k1 < 16; k1++) {
        long a = base + (long)(16 * k1 + u) * stride;
        float rr = xr[k1] * scale, ii = xi[k1] * scale;
        if (cout)      cout[a] = make_float2(rr, ii);
        else if (amp)  { amp[a] = sqrtf(rr * rr + ii * ii); ph[a] = atan2f(ii, rr); }
        else           rout[a] = rr;
    }
}

// ---------------- router ----------------
__global__ void gap_kernel(const float* __restrict__ vis, const float* __restrict__ ir,
                           float* __restrict__ gm) {
    __shared__ float red[256];
    int b = blockIdx.x >> 7;
    int ch = blockIdx.x & 127;
    const float* p = (ch < 64) ? (vis + (long)(b * 64 + ch) * 65536)
                               : (ir  + (long)(b * 64 + ch - 64) * 65536);
    float s = 0.f;
    for (int i = threadIdx.x; i < 65536; i += 256) s += p[i];
    red[threadIdx.x] = s;
    __syncthreads();
    for (int st = 128; st > 0; st >>= 1) {
        if (threadIdx.x < st) red[threadIdx.x] += red[threadIdx.x + st];
        __syncthreads();
    }
    if (threadIdx.x == 0) gm[blockIdx.x] = red[0] * (1.0f / 65536.0f);
}

__global__ void router_kernel(const float* __restrict__ gm, const float* __restrict__ Wr,
                              const float* __restrict__ br, const float* __restrict__ bank,
                              float* __restrict__ intent) {
    __shared__ float pf[4][64];
    __shared__ float lg[4][4];
    __shared__ float w[4][4];
    int t = threadIdx.x;
    for (int b = 0; b < 4; b++) {
        float s = br[t];
        for (int c = 0; c < 128; c++) s += gm[b * 128 + c] * Wr[c * 64 + t];
        pf[b][t] = s;
    }
    __syncthreads();
    if (t < 16) {
        int b = t >> 2, j = t & 3;
        float s = 0.f;
        for (int p = 0; p < 64; p++) s += pf[b][p] * bank[j * 64 + p];
        lg[b][j] = s;
    }
    __syncthreads();
    if (t < 4) {
        int b = t;
        float m = fmaxf(fmaxf(lg[b][0], lg[b][1]), fmaxf(lg[b][2], lg[b][3]));
        float e0 = expf(lg[b][0] - m), e1 = expf(lg[b][1] - m);
        float e2 = expf(lg[b][2] - m), e3 = expf(lg[b][3] - m);
        float s = e0 + e1 + e2 + e3;
        w[b][0] = e0 / s; w[b][1] = e1 / s; w[b][2] = e2 / s; w[b][3] = e3 / s;
    }
    __syncthreads();
    for (int b = 0; b < 4; b++) {
        float s = 0.f;
        for (int j = 0; j < 4; j++) s += w[b][j] * bank[j * 64 + t];
        intent[b * 64 + t] = s;
    }
}

// ---------------- fused score net, branch-batched, FMA2 inner ----------------
__global__ void __launch_bounds__(256) score_fused_kernel(
        const float* __restrict__ ampV, const float* __restrict__ ampI,
        const float* __restrict__ phV, const float* __restrict__ phI,
        const float* __restrict__ intent,
        const float* __restrict__ aW1, const float* __restrict__ ab1,
        const float* __restrict__ aW2, const float* __restrict__ ab2,
        const float* __restrict__ pW1, const float* __restrict__ pb1,
        const float* __restrict__ pW2, const float* __restrict__ pb2,
        float* __restrict__ score) {
    const int BM = 64, BK = 16;
    __shared__ float As[BK][68];
    __shared__ float Bs[BK][132];
    __shared__ float red[64 * 16];
    int brx = blockIdx.y;
    const float* mapV = brx ? phV : ampV;
    const float* mapI = brx ? phI : ampI;
    const float* W1 = brx ? pW1 : aW1;
    const float* b1 = brx ? pb1 : ab1;
    const float* W2 = brx ? pW2 : aW2;
    const float* b2 = brx ? pb2 : ab2;

    int tid = threadIdx.x;
    int row0 = blockIdx.x * BM;
    int ty = tid >> 4, tx = tid & 15;

    ull acc2[4][4];
    #pragma unroll
    for (int i = 0; i < 4; i++)
        #pragma unroll
        for (int jp = 0; jp < 4; jp++) acc2[i][jp] = 0ull;

    for (int k0 = 0; k0 < SF_; k0 += BK) {
        #pragma unroll
        for (int lq = 0; lq < 4; lq++) {
            int e = tid + lq * 256;
            int r = e >> 4, c = e & 15;
            int col = k0 + c;
            int tok = row0 + r;
            int b = tok >> 12, n = tok & 4095;
            float v = 0.f;
            if (col < 2048) {
                int t = col & 1023;
                int ch = t >> 4, py = (t >> 2) & 3, px = t & 3;
                int hy = n >> 6, wx = n & 63;
                long m = (((long)(b * 64 + ch) * 256) + hy * 4 + py) * 256 + wx * 4 + px;
                v = (col < 1024) ? mapV[m] : mapI[m];
            } else if (col < SF_) {
                if (col == 2048)      v = (float)(n >> 6) * (1.0f / 63.0f);
                else if (col == 2049) v = (float)(n & 63) * (1.0f / 63.0f);
                else                  v = intent[b * 64 + (col - 2050)];
            }
            As[c][r] = v;
        }
        #pragma unroll
        for (int lq = 0; lq < 8; lq++) {
            int e = tid + lq * 256;
            int r = e >> 7, c = e & 127;
            Bs[r][c] = (k0 + r < SF_) ? W1[(long)(k0 + r) * 128 + c] : 0.f;
        }
        __syncthreads();
        #pragma unroll
        for (int kk = 0; kk < BK; kk++) {
            float4 av = *(const float4*)&As[kk][ty * 4];
            ull a2[4] = {pk2(av.x, av.x), pk2(av.y, av.y), pk2(av.z, av.z), pk2(av.w, av.w)};
            const ull* bp = (const ull*)&Bs[kk][tx * 8];
            ull b2v[4] = {bp[0], bp[1], bp[2], bp[3]};
            #pragma unroll
            for (int i = 0; i < 4; i++)
                #pragma unroll
                for (int jp = 0; jp < 4; jp++)
                    FMA2_(acc2[i][jp], a2[i], b2v[jp]);
        }
        __syncthreads();
    }

    float w2[8], bs[8];
    #pragma unroll
    for (int j = 0; j < 8; j++) { w2[j] = W2[tx * 8 + j]; bs[j] = b1[tx * 8 + j]; }
    #pragma unroll
    for (int i = 0; i < 4; i++) {
        float p = 0.f;
        #pragma unroll
        for (int jp = 0; jp < 4; jp++) {
            float c0, c1;
            upk2(acc2[i][jp], c0, c1);
            float h0 = fmaxf(c0 + bs[2 * jp], 0.f);
            float h1 = fmaxf(c1 + bs[2 * jp + 1], 0.f);
            p += h0 * w2[2 * jp] + h1 * w2[2 * jp + 1];
        }
        red[(ty * 4 + i) * 16 + tx] = p;
    }
    __syncthreads();
    if (tid < 64) {
        float s = 0.f;
        #pragma unroll
        for (int q = 0; q < 16; q++) s += red[tid * 16 + q];
        score[brx * NT_ + row0 + tid] = s + b2[0];
    }
}

// ---------------- batched 64x128 FMA2 GEMM: C = A@W (+residual) ----------------
struct GB { const float* A; const float* W; float* C; const float* R; };
struct GB8 { GB g[8]; };

__global__ void __launch_bounds__(256) gemm_batched_kernel(GB8 gb, int M, int N, int K) {
    const int BK = 16;
    __shared__ float As[BK][68];
    __shared__ float Bs[BK][132];
    GB p = gb.g[blockIdx.z];
    int tid = threadIdx.x;
    int row0 = blockIdx.y * 64, col0 = blockIdx.x * 128;
    int ty = tid >> 4, tx = tid & 15;

    ull acc2[4][4];
    #pragma unroll
    for (int i = 0; i < 4; i++)
        #pragma unroll
        for (int jp = 0; jp < 4; jp++) acc2[i][jp] = 0ull;

    for (int k0 = 0; k0 < K; k0 += BK) {
        #pragma unroll
        for (int lq = 0; lq < 4; lq++) {
            int e = tid + lq * 256;
            int r = e >> 4, c = e & 15;
            As[c][r] = p.A[(long)(row0 + r) * K + (k0 + c)];
        }
        #pragma unroll
        for (int lq = 0; lq < 8; lq++) {
            int e = tid + lq * 256;
            int r = e >> 7, c = e & 127;
            Bs[r][c] = p.W[(long)(k0 + r) * N + (col0 + c)];
        }
        __syncthreads();
        #pragma unroll
        for (int kk = 0; kk < BK; kk++) {
            float4 av = *(const float4*)&As[kk][ty * 4];
            ull a2[4] = {pk2(av.x, av.x), pk2(av.y, av.y), pk2(av.z, av.z), pk2(av.w, av.w)};
            const ull* bp = (const ull*)&Bs[kk][tx * 8];
            ull b2v[4] = {bp[0], bp[1], bp[2], bp[3]};
            #pragma unroll
            for (int i = 0; i < 4; i++)
                #pragma unroll
                for (int jp = 0; jp < 4; jp++)
                    FMA2_(acc2[i][jp], a2[i], b2v[jp]);
        }
        __syncthreads();
    }
    #pragma unroll
    for (int i = 0; i < 4; i++) {
        long r = row0 + ty * 4 + i;
        #pragma unroll
        for (int jp = 0; jp < 4; jp++) {
            float v0, v1;
            upk2(acc2[i][jp], v0, v1);
            long c0 = col0 + tx * 8 + 2 * jp;
            if (p.R) {
                v0 += p.R[r * N + c0];
                v1 += p.R[r * N + c0 + 1];
            }
            p.C[r * N + c0]     = v0;
            p.C[r * N + c0 + 1] = v1;
        }
    }
}

// ---------------- top-k via bitonic sort (branch-batched) ----------------
__global__ void __launch_bounds__(1024) topk_kernel(const float* __restrict__ score,
                                                    int* __restrict__ idxo) {
    __shared__ float key[4096];
    __shared__ int val[4096];
    int b4 = blockIdx.x;
    int brx = b4 >> 2, b = b4 & 3;
    int t = threadIdx.x;
    const float* sp = score + brx * NT_ + b * 4096;
    for (int i = t; i < 4096; i += 1024) { key[i] = sp[i]; val[i] = i; }
    __syncthreads();
    for (int k = 2; k <= 4096; k <<= 1) {
        for (int j = k >> 1; j > 0; j >>= 1) {
            for (int i = t; i < 4096; i += 1024) {
                int ixj = i ^ j;
                if (ixj > i) {
                    bool desc = ((i & k) == 0);
                    float a = key[i], c = key[ixj];
                    bool sw = desc ? (a < c) : (a > c);
                    if (sw) {
                        key[i] = c; key[ixj] = a;
                        int tv = val[i]; val[i] = val[ixj]; val[ixj] = tv;
                    }
                }
            }
            __syncthreads();
        }
    }
    if (t < 1024) idxo[b4 * 1024 + t] = val[t];
}

// ---------------- gather / scatter (branch-batched) ----------------
__device__ __forceinline__ long patch_pixel(int b, int n, int t) {
    int hy = n >> 6, wx = n & 63;
    int c = t >> 4, py = (t >> 2) & 3, px = t & 3;
    return (((long)(b * 64 + c) * 256) + hy * 4 + py) * 256 + wx * 4 + px;
}

__global__ void gather_kernel(const float* __restrict__ ampV, const float* __restrict__ ampI,
                              const float* __restrict__ phV, const float* __restrict__ phI,
                              const int* __restrict__ idx,
                              float* __restrict__ selV, float* __restrict__ selI) {
    int brx = blockIdx.y;
    const float* mapV = brx ? phV : ampV;
    const float* mapI = brx ? phI : ampI;
    long gid = (long)blockIdx.x * 256 + threadIdx.x;
    int bi = (int)(gid >> 10);
    int t = (int)(gid & 1023);
    int b = bi >> 10;
    int n = idx[brx * 4096 + bi];
    long m = patch_pixel(b, n, t);
    long off = (long)brx * SELSZ_;
    selV[off + gid] = mapV[m];
    selI[off + gid] = mapI[m];
}

__global__ void scatter_kernel(const float* __restrict__ fs, const int* __restrict__ idx,
                               float* __restrict__ faMap, float* __restrict__ fpMap) {
    int brx = blockIdx.y;
    float* outMap = brx ? fpMap : faMap;
    long gid = (long)blockIdx.x * 256 + threadIdx.x;
    int bi = (int)(gid >> 10);
    int t = (int)(gid & 1023);
    int b = bi >> 10;
    int n = idx[brx * 4096 + bi];
    long m = patch_pixel(b, n, t);
    outMap[m] = fs[(long)brx * SELSZ_ + gid];
}

// ---------------- attention: scores + split-softmax partials ----------------
__global__ void __launch_bounds__(256) attn_scores_kernel(
        const float* __restrict__ Q, const float* __restrict__ Kt,
        float* __restrict__ S, float* __restrict__ pmax, float* __restrict__ psum) {
    __shared__ __align__(16) float Qs[64][33];
    __shared__ __align__(16) float KsT[32][66];   // [d][j], even stride for ull loads
    __shared__ float rmaxS[64][17];
    __shared__ float rsumS[64][17];
    int z = blockIdx.z;                 // 0..31 = br*16 + (b*4+h)
    int brx = z >> 4, zz = z & 15;
    int b = zz >> 2, h = zz & 3;
    const float* Qp = Q + (long)brx * QSZ_ + (long)b * 1024 * 128 + h * 32;
    const float* Kp = Kt + (long)brx * QSZ_ + (long)b * 1024 * 128 + h * 32;
    int i0 = blockIdx.y * 64, j0 = blockIdx.x * 64;
    int tid = threadIdx.x;
    #pragma unroll
    for (int l = 0; l < 8; l++) {
        int e = tid + l * 256;
        int r = e >> 5, c = e & 31;
        Qs[r][c] = Qp[(long)(i0 + r) * 128 + c];
        KsT[c][r] = Kp[(long)(j0 + r) * 128 + c];
    }
    __syncthreads();
    int ty = tid >> 4, tx = tid & 15;
    ull acc2[4][2];
    #pragma unroll
    for (int i = 0; i < 4; i++) { acc2[i][0] = 0ull; acc2[i][1] = 0ull; }
    #pragma unroll
    for (int d = 0; d < 32; d++) {
        const ull* bp = (const ull*)&KsT[d][tx * 4];
        ull b0 = bp[0], b1 = bp[1];
        #pragma unroll
        for (int i = 0; i < 4; i++) {
            float a = Qs[ty * 4 + i][d];
            ull a2 = pk2(a, a);
            FMA2_(acc2[i][0], a2, b0);
            FMA2_(acc2[i][1], a2, b1);
        }
    }
    const float scale = 0.17677669529663687f;
    float sc[4][4];
    #pragma unroll
    for (int i = 0; i < 4; i++) {
        upk2(acc2[i][0], sc[i][0], sc[i][1]);
        upk2(acc2[i][1], sc[i][2], sc[i][3]);
        float m = -3.4e38f;
        #pragma unroll
        for (int j = 0; j < 4; j++) { sc[i][j] *= scale; m = fmaxf(m, sc[i][j]); }
        // vectorized store of the 4 contiguous cols
        *(float4*)&S[((long)z * 1024 + i0 + ty * 4 + i) * 1024 + j0 + tx * 4] =
            make_float4(sc[i][0], sc[i][1], sc[i][2], sc[i][3]);
        rmaxS[ty * 4 + i][tx] = m;
    }
    __syncthreads();
    if (tid < 64) {
        float m = rmaxS[tid][0];
        #pragma unroll
        for (int q = 1; q < 16; q++) m = fmaxf(m, rmaxS[tid][q]);
        rmaxS[tid][16] = m;
    }
    __syncthreads();
    #pragma unroll
    for (int i = 0; i < 4; i++) {
        float m = rmaxS[ty * 4 + i][16];
        float p = 0.f;
        #pragma unroll
        for (int j = 0; j < 4; j++) p += __expf(sc[i][j] - m);
        rsumS[ty * 4 + i][tx] = p;
    }
    __syncthreads();
    if (tid < 64) {
        float s = 0.f;
        #pragma unroll
        for (int q = 0; q < 16; q++) s += rsumS[tid][q];
        long ridx = ((long)z * 1024 + i0 + tid) * 16 + blockIdx.x;
        pmax[ridx] = rmaxS[tid][16];
        psum[ridx] = s;
    }
}

// ---------------- attention: combine split-softmax partials per row ----------------
__global__ void attn_reduce_kernel(const float* __restrict__ pmax,
                                   const float* __restrict__ psum,
                                   float* __restrict__ gmax, float* __restrict__ gsum) {
    int r = blockIdx.x * 256 + threadIdx.x;     // 0..32767
    const float* pm = pmax + (long)r * 16;
    const float* ps = psum + (long)r * 16;
    float m = pm[0];
    #pragma unroll
    for (int q = 1; q < 16; q++) m = fmaxf(m, pm[q]);
    float s = 0.f;
    #pragma unroll
    for (int q = 0; q < 16; q++) s += ps[q] * __expf(pm[q] - m);
    gmax[r] = m;
    gsum[r] = s;
}

// ---------------- attention: apply (exp on load, FMA2, normalize at end) ----------------
__global__ void __launch_bounds__(256) attn_apply_kernel(
        const float* __restrict__ S, const float* __restrict__ V,
        const float* __restrict__ gmax, const float* __restrict__ gsum,
        float* __restrict__ O) {
    __shared__ __align__(16) float Ps[64][66];
    __shared__ __align__(16) float Vs[64][34];
    __shared__ float gmr[64], gsr[64];
    int z = blockIdx.y;                 // 0..31
    int brx = z >> 4, zz = z & 15;
    int b = zz >> 2, h = zz & 3;
    int i0 = blockIdx.x * 64;
    int tid = threadIdx.x;
    int ty = tid >> 4, tx = tid & 15;
    const float* Vp = V + (long)brx * QSZ_;
    float* Op = O + (long)brx * QSZ_;
    if (tid < 64) {
        gmr[tid] = gmax[(long)z * 1024 + i0 + tid];
        gsr[tid] = gsum[(long)z * 1024 + i0 + tid];
    }
    __syncthreads();
    ull acc2[4];
    #pragma unroll
    for (int i = 0; i < 4; i++) acc2[i] = 0ull;
    for (int j0 = 0; j0 < 1024; j0 += 64) {
        #pragma unroll
        for (int l = 0; l < 16; l++) {
            int e = tid + l * 256;
            int r = e >> 6, c = e & 63;
            float s = S[((long)z * 1024 + i0 + r) * 1024 + j0 + c];
            Ps[r][c] = __expf(s - gmr[r]);
        }
        #pragma unroll
        for (int l = 0; l < 8; l++) {
            int e = tid + l * 256;
            int r = e >> 5, c = e & 31;
            Vs[r][c] = Vp[(long)(b * 1024 + j0 + r) * 128 + h * 32 + c];
        }
        __syncthreads();
        #pragma unroll
        for (int kk = 0; kk < 64; kk++) {
            ull v2 = *(const ull*)&Vs[kk][tx * 2];
            #pragma unroll
            for (int i = 0; i < 4; i++) {
                float a = Ps[ty * 4 + i][kk];
                FMA2_(acc2[i], pk2(a, a), v2);
            }
        }
        __syncthreads();
    }
    #pragma unroll
    for (int i = 0; i < 4; i++) {
        float v0, v1;
        upk2(acc2[i], v0, v1);
        float inv = 1.0f / gsr[ty * 4 + i];
        long obase = (long)(b * 1024 + i0 + ty * 4 + i) * 128 + h * 32 + tx * 2;
        Op[obase]     = v0 * inv;
        Op[obase + 1] = v1 * inv;
    }
}

// ---------------- elementwise avg (branch-batched) ----------------
__global__ void avg_kernel(const float* __restrict__ ampV, const float* __restrict__ ampI,
                           float* __restrict__ faMap,
                           const float* __restrict__ phV, const float* __restrict__ phI,
                           float* __restrict__ fpMap) {
    int brx = blockIdx.y;
    long i = (long)blockIdx.x * 256 + threadIdx.x;
    if (brx == 0) faMap[i] = 0.5f * (ampV[i] + ampI[i]);
    else          fpMap[i] = 0.5f * (phV[i] + phI[i]);
}

// ---------------- 3x3 SAME conv: 16x16 tile, 64 co/block, channel-pair FMA2 ----------------
__global__ void __launch_bounds__(256) conv3_kernel(
        const float* __restrict__ in, const float* __restrict__ wgt,
        const float* __restrict__ bias, float* __restrict__ out,
        const float* __restrict__ resA, const float* __restrict__ resB,
        int relu) {
    __shared__ float sIn[18][18];
    __shared__ float2 sW2[32][9];
    int bz = blockIdx.z;
    int x0 = blockIdx.x * 16, y0 = blockIdx.y * 16;
    int tx = threadIdx.x & 15, ty = threadIdx.x >> 4;
    int tid = threadIdx.x;
    int x = x0 + tx, y = y0 + ty;

    ull acc[32];
    #pragma unroll
    for (int p = 0; p < 32; p++) acc[p] = 0ull;

    for (int ci = 0; ci < 64; ci++) {
        const float* ip = in + (long)(bz * 64 + ci) * 65536;
        for (int e = tid; e < 324; e += 256) {
            int ry = e / 18, rx = e % 18;
            int gy = y0 + ry - 1, gx = x0 + rx - 1;
            sIn[ry][rx] = (gy >= 0 && gy < 256 && gx >= 0 && gx < 256) ? ip[gy * 256 + gx] : 0.f;
        }
        for (int e = tid; e < 288; e += 256) {
            int p = e / 9, k = e % 9;
            sW2[p][k] = make_float2(wgt[((long)(2 * p) * 64 + ci) * 9 + k],
                                    wgt[((long)(2 * p + 1) * 64 + ci) * 9 + k]);
        }
        __syncthreads();
        ull vp[9];
        #pragma unroll
        for (int ky = 0; ky < 3; ky++)
            #pragma unroll
            for (int kx = 0; kx < 3; kx++) {
                float v = sIn[ty + ky][tx + kx];
                vp[ky * 3 + kx] = pk2(v, v);
            }
        #pragma unroll
        for (int p = 0; p < 32; p++) {
            #pragma unroll
            for (int k = 0; k < 9; k++) {
                ull w2 = *(const ull*)&sW2[p][k];
                FMA2_(acc[p], vp[k], w2);
            }
        }
        __syncthreads();
    }
    #pragma unroll
    for (int p = 0; p < 32; p++) {
        float v0, v1;
        upk2(acc[p], v0, v1);
        int co0 = 2 * p, co1 = 2 * p + 1;
        long o0 = ((long)(bz * 64 + co0) * 256 + y) * 256 + x;
        long o1 = ((long)(bz * 64 + co1) * 256 + y) * 256 + x;
        v0 += bias[co0];
        v1 += bias[co1];
        if (relu) { v0 = fmaxf(v0, 0.f); v1 = fmaxf(v1, 0.f); }
        if (resA) {
            v0 += 0.5f * (resA[o0] + resB[o0]);
            v1 += 0.5f * (resA[o1] + resB[o1]);
        }
        out[o0] = v0;
        out[o1] = v1;
    }
}

extern "C" void kernel_launch(void* const* d_in, const int* in_sizes, int n_in,
                              void* d_out, int out_size) {
    const float* vis  = (const float*)d_in[0];
    const float* ir   = (const float*)d_in[1];
    const float* bank = (const float*)d_in[2];
    const float* Wr   = (const float*)d_in[3];
    const float* br   = (const float*)d_in[4];
    const float* aW1  = (const float*)d_in[5];
    const float* ab1  = (const float*)d_in[6];
    const float* aW2  = (const float*)d_in[7];
    const float* ab2  = (const float*)d_in[8];
    const float* aWq  = (const float*)d_in[9];
    const float* aWk  = (const float*)d_in[10];
    const float* aWv  = (const float*)d_in[11];
    const float* aWo  = (const float*)d_in[12];
    const float* pW1  = (const float*)d_in[13];
    const float* pb1  = (const float*)d_in[14];
    const float* pW2  = (const float*)d_in[15];
    const float* pb2  = (const float*)d_in[16];
    const float* pWq  = (const float*)d_in[17];
    const float* pWk  = (const float*)d_in[18];
    const float* pWv  = (const float*)d_in[19];
    const float* pWo  = (const float*)d_in[20];
    const float* c1w  = (const float*)d_in[21];
    const float* c1b  = (const float*)d_in[22];
    const float* c2w  = (const float*)d_in[23];
    const float* c2b  = (const float*)d_in[24];
    float* out = (float*)d_out;

    float2* cA;
    float *ampV, *ampI, *phV, *phI, *faMap, *fpMap, *spatial, *r1;
    float *score, *selV, *selI, *q, *k, *v, *o, *att, *fs, *gm, *intent;
    float *pmax, *psum, *gmaxp, *gsump;
    int* idxp;
    cudaGetSymbolAddress((void**)&cA, g_cA);
    cudaGetSymbolAddress((void**)&ampV, g_ampV);
    cudaGetSymbolAddress((void**)&ampI, g_ampI);
    cudaGetSymbolAddress((void**)&phV, g_phV);
    cudaGetSymbolAddress((void**)&phI, g_phI);
    cudaGetSymbolAddress((void**)&faMap, g_faMap);
    cudaGetSymbolAddress((void**)&fpMap, g_fpMap);
    cudaGetSymbolAddress((void**)&spatial, g_spatial);
    cudaGetSymbolAddress((void**)&r1, g_r1);
    cudaGetSymbolAddress((void**)&score, g_scoreArr);
    cudaGetSymbolAddress((void**)&idxp, g_idxArr);
    cudaGetSymbolAddress((void**)&selV, g_selV);
    cudaGetSymbolAddress((void**)&selI, g_selI);
    cudaGetSymbolAddress((void**)&q, g_qb);
    cudaGetSymbolAddress((void**)&k, g_kb);
    cudaGetSymbolAddress((void**)&v, g_vb);
    cudaGetSymbolAddress((void**)&o, g_ob);
    cudaGetSymbolAddress((void**)&att, g_att);
    cudaGetSymbolAddress((void**)&fs, g_fs);
    cudaGetSymbolAddress((void**)&gm, g_gm);
    cudaGetSymbolAddress((void**)&intent, g_intentArr);
    cudaGetSymbolAddress((void**)&pmax, g_pmax);
    cudaGetSymbolAddress((void**)&psum, g_psum);
    cudaGetSymbolAddress((void**)&gmaxp, g_gmax);
    cudaGetSymbolAddress((void**)&gsump, g_gsum);

    twiddle_init_kernel<<<1, 256>>>();
    gap_kernel<<<512, 256>>>(vis, ir, gm);
    router_kernel<<<1, 64>>>(gm, Wr, br, bank, intent);

    const int FB = 4096;
    fft_pass2_kernel<<<FB, 256>>>(nullptr, vis, nullptr, nullptr, cA, nullptr, nullptr, nullptr, 0, +1, 1.f);
    fft_pass2_kernel<<<FB, 256>>>(cA, nullptr, nullptr, nullptr, nullptr, ampV, phV, nullptr, 1, +1, 1.f);
    fft_pass2_kernel<<<FB, 256>>>(nullptr, ir, nullptr, nullptr, cA, nullptr, nullptr, nullptr, 0, +1, 1.f);
    fft_pass2_kernel<<<FB, 256>>>(cA, nullptr, nullptr, nullptr, nullptr, ampI, phI, nullptr, 1, +1, 1.f);

    // ----- batched branch pipeline -----
    score_fused_kernel<<<dim3(256, 2), 256>>>(ampV, ampI, phV, phI, intent,
                                              aW1, ab1, aW2, ab2, pW1, pb1, pW2, pb2, score);
    topk_kernel<<<8, 1024>>>(score, idxp);
    gather_kernel<<<dim3(16384, 2), 256>>>(ampV, ampI, phV, phI, idxp, selV, selI);

    GB8 qkv;
    qkv.g[0] = { selV,          aWq, q,          nullptr };
    qkv.g[1] = { selI,          aWk, k,          nullptr };
    qkv.g[2] = { selI,          aWv, v,          nullptr };
    qkv.g[3] = { selV + SELSZ_, pWq, q + QSZ_,   nullptr };
    qkv.g[4] = { selI + SELSZ_, pWk, k + QSZ_,   nullptr };
    qkv.g[5] = { selI + SELSZ_, pWv, v + QSZ_,   nullptr };
    qkv.g[6] = { nullptr, nullptr, nullptr, nullptr };
    qkv.g[7] = { nullptr, nullptr, nullptr, nullptr };
    gemm_batched_kernel<<<dim3(1, 64, 6), 256>>>(qkv, 4096, 128, 1024);

    attn_scores_kernel<<<dim3(16, 16, 32), 256>>>(q, k, att, pmax, psum);
    attn_reduce_kernel<<<128, 256>>>(pmax, psum, gmaxp, gsump);
    attn_apply_kernel<<<dim3(16, 32), 256>>>(att, v, gmaxp, gsump, o);

    GB8 wo;
    wo.g[0] = { o,        aWo, fs,          selV };
    wo.g[1] = { o + QSZ_, pWo, fs + SELSZ_, selV + SELSZ_ };
    for (int z = 2; z < 8; z++) wo.g[z] = { nullptr, nullptr, nullptr, nullptr };
    gemm_batched_kernel<<<dim3(8, 64, 2), 256>>>(wo, 4096, 1024, 128);

    avg_kernel<<<dim3(65536, 2), 256>>>(ampV, ampI, faMap, phV, phI, fpMap);
    scatter_kernel<<<dim3(16384, 2), 256>>>(fs, idxp, faMap, fpMap);

    fft_pass2_kernel<<<FB, 256>>>(nullptr, nullptr, faMap, fpMap, cA, nullptr, nullptr, nullptr, 0, -1, 1.f);
    fft_pass2_kernel<<<FB, 256>>>(cA, nullptr, nullptr, nullptr, nullptr, nullptr, nullptr, spatial, 1, -1, 1.0f / 65536.0f);

    conv3_kernel<<<dim3(16, 16, 4), 256>>>(spatial, c1w, c1b, r1, nullptr, nullptr, 1);
    conv3_kernel<<<dim3(16, 16, 4), 256>>>(r1, c2w, c2b, out, vis, ir, 0);

    (void)in_sizes; (void)n_in; (void)out_size;
}

// round 12
// speedup vs baseline: 1.0034x; 1.0033x over previous
#include <cuda_runtime.h>
#include <math.h>

// ---------------- problem constants ----------------
#define B_    4
#define C_    64
#define NPIX_ 16777216            // B*C*H*W
#define NT_   16384               // B * NPAT
#define TOK_  1024
#define SF_   2114
#define KSEL_ 1024
#define E_    128
#define SELSZ_ ((long)B_ * KSEL_ * TOK_)
#define QSZ_   (B_ * KSEL_ * E_)
#define ATTSZ_ ((long)B_ * 4 * KSEL_ * KSEL_)
#define NROWS_ (32 * 1024)        // (2 branches * 16 z) * 1024 rows

typedef unsigned long long ull;

// ---------------- device scratch (2x for batched branches) ----------------
__device__ float2 g_cA[NPIX_];
__device__ float  g_ampV[NPIX_];
__device__ float  g_ampI[NPIX_];
__device__ float  g_phV [NPIX_];
__device__ float  g_phI [NPIX_];
__device__ float  g_faMap[NPIX_];
__device__ float  g_fpMap[NPIX_];
__device__ float  g_spatial[NPIX_];
__device__ float  g_r1[NPIX_];
__device__ float  g_scoreArr[2 * NT_];
__device__ int    g_idxArr[2 * B_ * KSEL_];
__device__ float  g_selV[2 * SELSZ_];
__device__ float  g_selI[2 * SELSZ_];
__device__ float  g_qb[2 * QSZ_];
__device__ float  g_kb[2 * QSZ_];
__device__ float  g_vb[2 * QSZ_];
__device__ float  g_ob[2 * QSZ_];
__device__ float  g_att[2 * ATTSZ_];
__device__ float  g_fs[2 * SELSZ_];
__device__ float  g_gm[B_ * 2 * C_];
__device__ float  g_intentArr[B_ * 64];
__device__ float  g_t256r[256];
__device__ float  g_t256i[256];
__device__ float  g_pmax[NROWS_ * 16];
__device__ float  g_psum[NROWS_ * 16];
__device__ float  g_gmax[NROWS_];
__device__ float  g_gsum[NROWS_];

// ---------------- packed f32x2 helpers (sm_103a FFMA2) ----------------
__device__ __forceinline__ ull pk2(float lo, float hi) {
    ull r;
    asm("mov.b64 %0, {%1, %2};" : "=l"(r) : "f"(lo), "f"(hi));
    return r;
}
__device__ __forceinline__ void upk2(ull v, float& lo, float& hi) {
    asm("mov.b64 {%0, %1}, %2;" : "=f"(lo), "=f"(hi) : "l"(v));
}
#define FMA2_(d, a, b) asm("fma.rn.f32x2 %0, %1, %2, %0;" : "+l"(d) : "l"(a), "l"(b))

// ---------------- twiddles ----------------
__global__ void twiddle_init_kernel() {
    int k = threadIdx.x;
    double a = -2.0 * 3.14159265358979323846 * (double)k / 256.0;
    g_t256r[k] = (float)cos(a);
    g_t256i[k] = (float)sin(a);
}

// ---------------- 16-point register FFT ----------------
__device__ __forceinline__ void fft16_reg(float* xr, float* xi, float dsign) {
    #define SW16_(a,b) { float t=xr[a]; xr[a]=xr[b]; xr[b]=t; t=xi[a]; xi[a]=xi[b]; xi[b]=t; }
    SW16_(1,8) SW16_(2,4) SW16_(3,12) SW16_(5,10) SW16_(7,14) SW16_(11,13)
    #undef SW16_
    const float C16[8] = {1.f, 0.9238795325112867f, 0.7071067811865476f, 0.3826834323650898f,
                          0.f, -0.3826834323650898f, -0.7071067811865476f, -0.9238795325112867f};
    const float S16[8] = {0.f, 0.3826834323650898f, 0.7071067811865476f, 0.9238795325112867f,
                          1.f, 0.9238795325112867f, 0.7071067811865476f, 0.3826834323650898f};
    #pragma unroll
    for (int s = 1; s <= 4; s++) {
        const int half = 1 << (s - 1);
        #pragma unroll
        for (int j = 0; j < 8; j++) {
            const int grp = j >> (s - 1);
            const int pos = j & (half - 1);
            const int i = (grp << s) + pos;
            const int l = i + half;
            const int ti = pos << (4 - s);
            float wr = C16[ti];
            float wi = -dsign * S16[ti];
            float vr = xr[l] * wr - xi[l] * wi;
            float vi = xr[l] * wi + xi[l] * wr;
            float ur = xr[i], ui = xi[i];
            xr[i] = ur + vr; xi[i] = ui + vi;
            xr[l] = ur - vr; xi[l] = ui - vi;
        }
    }
}

// ---------------- 256-pt FFT pass ----------------
#define FFT_SM 4352
__global__ void fft_pass2_kernel(const float2* __restrict__ cin,
                                 const float* __restrict__ rin,
                                 const float* __restrict__ fa,
                                 const float* __restrict__ fp,
                                 float2* __restrict__ cout,
                                 float* __restrict__ amp,
                                 float* __restrict__ ph,
                                 float* __restrict__ rout,
                                 int colmode, int dir, float scale) {
    __shared__ float sre[FFT_SM];
    __shared__ float sim[FFT_SM];
    int tid = threadIdx.x;
    int tx = tid & 15, ty = tid >> 4;
    int u = colmode ? ty : tx;
    int s = colmode ? tx : ty;
    int line = blockIdx.x * 16 + s;
    int plane = line >> 8, l = line & 255;
    long base; int stride;
    if (colmode) { base = (long)plane * 65536 + l; stride = 256; }
    else         { base = (long)plane * 65536 + (long)l * 256; stride = 1; }
    float dsign = (dir > 0) ? 1.f : -1.f;

    float xr[16], xi[16];
    #pragma unroll
    for (int n2 = 0; n2 < 16; n2++) {
        long a = base + (long)(u + 16 * n2) * stride;
        if (rin)      { xr[n2] = rin[a]; xi[n2] = 0.f; }
        else if (fa)  { float am = fa[a]; float sn, cs; sincosf(fp[a], &sn, &cs);
                        xr[n2] = am * cs; xi[n2] = am * sn; }
        else          { float2 c = cin[a]; xr[n2] = c.x; xi[n2] = c.y; }
    }
    fft16_reg(xr, xi, dsign);
    #pragma unroll
    for (int k2 = 0; k2 < 16; k2++) {
        int m = u * k2;
        float wr = g_t256r[m];
        float wi = dsign * g_t256i[m];
        float a = xr[k2], b = xi[k2];
        xr[k2] = a * wr - b * wi;
        xi[k2] = a * wi + b * wr;
    }
    #pragma unroll
    for (int k2 = 0; k2 < 16; k2++) {
        int idx = colmode ? ((k2 * 16 + u) * 17 + s) : (s * 272 + k2 * 17 + u);
        sre[idx] = xr[k2]; sim[idx] = xi[k2];
    }
    __syncthreads();
    #pragma unroll
    for (int n1 = 0; n1 < 16; n1++) {
        int idx = colmode ? ((u * 16 + n1) * 17 + s) : (s * 272 + u * 17 + n1);
        xr[n1] = sre[idx]; xi[n1] = sim[idx];
    }
    fft16_reg(xr, xi, dsign);
    #pragma unroll
    for (int k1 = 0; k1 < 16; k1++) {
        long a = base + (long)(16 * k1 + u) * stride;
        float rr = xr[k1] * scale, ii = xi[k1] * scale;
        if (cout)      cout[a] = make_float2(rr, ii);
        else if (amp)  { amp[a] = sqrtf(rr * rr + ii * ii); ph[a] = atan2f(ii, rr); }
        else           rout[a] = rr;
    }
}

// ---------------- router ----------------
__global__ void gap_kernel(const float* __restrict__ vis, const float* __restrict__ ir,
                           float* __restrict__ gm) {
    __shared__ float red[256];
    int b = blockIdx.x >> 7;
    int ch = blockIdx.x & 127;
    const float* p = (ch < 64) ? (vis + (long)(b * 64 + ch) * 65536)
                               : (ir  + (long)(b * 64 + ch - 64) * 65536);
    float s = 0.f;
    for (int i = threadIdx.x; i < 65536; i += 256) s += p[i];
    red[threadIdx.x] = s;
    __syncthreads();
    for (int st = 128; st > 0; st >>= 1) {
        if (threadIdx.x < st) red[threadIdx.x] += red[threadIdx.x + st];
        __syncthreads();
    }
    if (threadIdx.x == 0) gm[blockIdx.x] = red[0] * (1.0f / 65536.0f);
}

__global__ void router_kernel(const float* __restrict__ gm, const float* __restrict__ Wr,
                              const float* __restrict__ br, const float* __restrict__ bank,
                              float* __restrict__ intent) {
    __shared__ float pf[4][64];
    __shared__ float lg[4][4];
    __shared__ float w[4][4];
    int t = threadIdx.x;
    for (int b = 0; b < 4; b++) {
        float s = br[t];
        for (int c = 0; c < 128; c++) s += gm[b * 128 + c] * Wr[c * 64 + t];
        pf[b][t] = s;
    }
    __syncthreads();
    if (t < 16) {
        int b = t >> 2, j = t & 3;
        float s = 0.f;
        for (int p = 0; p < 64; p++) s += pf[b][p] * bank[j * 64 + p];
        lg[b][j] = s;
    }
    __syncthreads();
    if (t < 4) {
        int b = t;
        float m = fmaxf(fmaxf(lg[b][0], lg[b][1]), fmaxf(lg[b][2], lg[b][3]));
        float e0 = expf(lg[b][0] - m), e1 = expf(lg[b][1] - m);
        float e2 = expf(lg[b][2] - m), e3 = expf(lg[b][3] - m);
        float s = e0 + e1 + e2 + e3;
        w[b][0] = e0 / s; w[b][1] = e1 / s; w[b][2] = e2 / s; w[b][3] = e3 / s;
    }
    __syncthreads();
    for (int b = 0; b < 4; b++) {
        float s = 0.f;
        for (int j = 0; j < 4; j++) s += w[b][j] * bank[j * 64 + t];
        intent[b * 64 + t] = s;
    }
}

// ---------------- fused score net, branch-batched, FMA2 inner ----------------
__global__ void __launch_bounds__(256) score_fused_kernel(
        const float* __restrict__ ampV, const float* __restrict__ ampI,
        const float* __restrict__ phV, const float* __restrict__ phI,
        const float* __restrict__ intent,
        const float* __restrict__ aW1, const float* __restrict__ ab1,
        const float* __restrict__ aW2, const float* __restrict__ ab2,
        const float* __restrict__ pW1, const float* __restrict__ pb1,
        const float* __restrict__ pW2, const float* __restrict__ pb2,
        float* __restrict__ score) {
    const int BM = 64, BK = 16;
    __shared__ float As[BK][68];
    __shared__ float Bs[BK][132];
    __shared__ float red[64 * 16];
    int brx = blockIdx.y;
    const float* mapV = brx ? phV : ampV;
    const float* mapI = brx ? phI : ampI;
    const float* W1 = brx ? pW1 : aW1;
    const float* b1 = brx ? pb1 : ab1;
    const float* W2 = brx ? pW2 : aW2;
    const float* b2 = brx ? pb2 : ab2;

    int tid = threadIdx.x;
    int row0 = blockIdx.x * BM;
    int ty = tid >> 4, tx = tid & 15;

    ull acc2[4][4];
    #pragma unroll
    for (int i = 0; i < 4; i++)
        #pragma unroll
        for (int jp = 0; jp < 4; jp++) acc2[i][jp] = 0ull;

    for (int k0 = 0; k0 < SF_; k0 += BK) {
        #pragma unroll
        for (int lq = 0; lq < 4; lq++) {
            int e = tid + lq * 256;
            int r = e >> 4, c = e & 15;
            int col = k0 + c;
            int tok = row0 + r;
            int b = tok >> 12, n = tok & 4095;
            float v = 0.f;
            if (col < 2048) {
                int t = col & 1023;
                int ch = t >> 4, py = (t >> 2) & 3, px = t & 3;
                int hy = n >> 6, wx = n & 63;
                long m = (((long)(b * 64 + ch) * 256) + hy * 4 + py) * 256 + wx * 4 + px;
                v = (col < 1024) ? mapV[m] : mapI[m];
            } else if (col < SF_) {
                if (col == 2048)      v = (float)(n >> 6) * (1.0f / 63.0f);
                else if (col == 2049) v = (float)(n & 63) * (1.0f / 63.0f);
                else                  v = intent[b * 64 + (col - 2050)];
            }
            As[c][r] = v;
        }
        #pragma unroll
        for (int lq = 0; lq < 8; lq++) {
            int e = tid + lq * 256;
            int r = e >> 7, c = e & 127;
            Bs[r][c] = (k0 + r < SF_) ? W1[(long)(k0 + r) * 128 + c] : 0.f;
        }
        __syncthreads();
        #pragma unroll
        for (int kk = 0; kk < BK; kk++) {
            float4 av = *(const float4*)&As[kk][ty * 4];
            ull a2[4] = {pk2(av.x, av.x), pk2(av.y, av.y), pk2(av.z, av.z), pk2(av.w, av.w)};
            const ull* bp = (const ull*)&Bs[kk][tx * 8];
            ull b2v[4] = {bp[0], bp[1], bp[2], bp[3]};
            #pragma unroll
            for (int i = 0; i < 4; i++)
                #pragma unroll
                for (int jp = 0; jp < 4; jp++)
                    FMA2_(acc2[i][jp], a2[i], b2v[jp]);
        }
        __syncthreads();
    }

    float w2[8], bs[8];
    #pragma unroll
    for (int j = 0; j < 8; j++) { w2[j] = W2[tx * 8 + j]; bs[j] = b1[tx * 8 + j]; }
    #pragma unroll
    for (int i = 0; i < 4; i++) {
        float p = 0.f;
        #pragma unroll
        for (int jp = 0; jp < 4; jp++) {
            float c0, c1;
            upk2(acc2[i][jp], c0, c1);
            float h0 = fmaxf(c0 + bs[2 * jp], 0.f);
            float h1 = fmaxf(c1 + bs[2 * jp + 1], 0.f);
            p += h0 * w2[2 * jp] + h1 * w2[2 * jp + 1];
        }
        red[(ty * 4 + i) * 16 + tx] = p;
    }
    __syncthreads();
    if (tid < 64) {
        float s = 0.f;
        #pragma unroll
        for (int q = 0; q < 16; q++) s += red[tid * 16 + q];
        score[brx * NT_ + row0 + tid] = s + b2[0];
    }
}

// ---------------- batched 64x128 FMA2 GEMM: C = A@W (+residual) ----------------
struct GB { const float* A; const float* W; float* C; const float* R; };
struct GB8 { GB g[8]; };

__global__ void __launch_bounds__(256) gemm_batched_kernel(GB8 gb, int M, int N, int K) {
    const int BK = 16;
    __shared__ float As[BK][68];
    __shared__ float Bs[BK][132];
    GB p = gb.g[blockIdx.z];
    int tid = threadIdx.x;
    int row0 = blockIdx.y * 64, col0 = blockIdx.x * 128;
    int ty = tid >> 4, tx = tid & 15;

    ull acc2[4][4];
    #pragma unroll
    for (int i = 0; i < 4; i++)
        #pragma unroll
        for (int jp = 0; jp < 4; jp++) acc2[i][jp] = 0ull;

    for (int k0 = 0; k0 < K; k0 += BK) {
        #pragma unroll
        for (int lq = 0; lq < 4; lq++) {
            int e = tid + lq * 256;
            int r = e >> 4, c = e & 15;
            As[c][r] = p.A[(long)(row0 + r) * K + (k0 + c)];
        }
        #pragma unroll
        for (int lq = 0; lq < 8; lq++) {
            int e = tid + lq * 256;
            int r = e >> 7, c = e & 127;
            Bs[r][c] = p.W[(long)(k0 + r) * N + (col0 + c)];
        }
        __syncthreads();
        #pragma unroll
        for (int kk = 0; kk < BK; kk++) {
            float4 av = *(const float4*)&As[kk][ty * 4];
            ull a2[4] = {pk2(av.x, av.x), pk2(av.y, av.y), pk2(av.z, av.z), pk2(av.w, av.w)};
            const ull* bp = (const ull*)&Bs[kk][tx * 8];
            ull b2v[4] = {bp[0], bp[1], bp[2], bp[3]};
            #pragma unroll
            for (int i = 0; i < 4; i++)
                #pragma unroll
                for (int jp = 0; jp < 4; jp++)
                    FMA2_(acc2[i][jp], a2[i], b2v[jp]);
        }
        __syncthreads();
    }
    #pragma unroll
    for (int i = 0; i < 4; i++) {
        long r = row0 + ty * 4 + i;
        #pragma unroll
        for (int jp = 0; jp < 4; jp++) {
            float v0, v1;
            upk2(acc2[i][jp], v0, v1);
            long c0 = col0 + tx * 8 + 2 * jp;
            if (p.R) {
                v0 += p.R[r * N + c0];
                v1 += p.R[r * N + c0 + 1];
            }
            p.C[r * N + c0]     = v0;
            p.C[r * N + c0 + 1] = v1;
        }
    }
}

// ---------------- top-k via bitonic sort (branch-batched) ----------------
__global__ void __launch_bounds__(1024) topk_kernel(const float* __restrict__ score,
                                                    int* __restrict__ idxo) {
    __shared__ float key[4096];
    __shared__ int val[4096];
    int b4 = blockIdx.x;
    int brx = b4 >> 2, b = b4 & 3;
    int t = threadIdx.x;
    const float* sp = score + brx * NT_ + b * 4096;
    for (int i = t; i < 4096; i += 1024) { key[i] = sp[i]; val[i] = i; }
    __syncthreads();
    for (int k = 2; k <= 4096; k <<= 1) {
        for (int j = k >> 1; j > 0; j >>= 1) {
            for (int i = t; i < 4096; i += 1024) {
                int ixj = i ^ j;
                if (ixj > i) {
                    bool desc = ((i & k) == 0);
                    float a = key[i], c = key[ixj];
                    bool sw = desc ? (a < c) : (a > c);
                    if (sw) {
                        key[i] = c; key[ixj] = a;
                        int tv = val[i]; val[i] = val[ixj]; val[ixj] = tv;
                    }
                }
            }
            __syncthreads();
        }
    }
    if (t < 1024) idxo[b4 * 1024 + t] = val[t];
}

// ---------------- gather / scatter (branch-batched) ----------------
__device__ __forceinline__ long patch_pixel(int b, int n, int t) {
    int hy = n >> 6, wx = n & 63;
    int c = t >> 4, py = (t >> 2) & 3, px = t & 3;
    return (((long)(b * 64 + c) * 256) + hy * 4 + py) * 256 + wx * 4 + px;
}

__global__ void gather_kernel(const float* __restrict__ ampV, const float* __restrict__ ampI,
                              const float* __restrict__ phV, const float* __restrict__ phI,
                              const int* __restrict__ idx,
                              float* __restrict__ selV, float* __restrict__ selI) {
    int brx = blockIdx.y;
    const float* mapV = brx ? phV : ampV;
    const float* mapI = brx ? phI : ampI;
    long gid = (long)blockIdx.x * 256 + threadIdx.x;
    int bi = (int)(gid >> 10);
    int t = (int)(gid & 1023);
    int b = bi >> 10;
    int n = idx[brx * 4096 + bi];
    long m = patch_pixel(b, n, t);
    long off = (long)brx * SELSZ_;
    selV[off + gid] = mapV[m];
    selI[off + gid] = mapI[m];
}

__global__ void scatter_kernel(const float* __restrict__ fs, const int* __restrict__ idx,
                               float* __restrict__ faMap, float* __restrict__ fpMap) {
    int brx = blockIdx.y;
    float* outMap = brx ? fpMap : faMap;
    long gid = (long)blockIdx.x * 256 + threadIdx.x;
    int bi = (int)(gid >> 10);
    int t = (int)(gid & 1023);
    int b = bi >> 10;
    int n = idx[brx * 4096 + bi];
    long m = patch_pixel(b, n, t);
    outMap[m] = fs[(long)brx * SELSZ_ + gid];
}

// ---------------- attention: scores + split-softmax partials ----------------
__global__ void __launch_bounds__(256) attn_scores_kernel(
        const float* __restrict__ Q, const float* __restrict__ Kt,
        float* __restrict__ S, float* __restrict__ pmax, float* __restrict__ psum) {
    __shared__ __align__(16) float Qs[64][33];
    __shared__ __align__(16) float KsT[32][66];   // [d][j], even stride for ull loads
    __shared__ float rmaxS[64][17];
    __shared__ float rsumS[64][17];
    int z = blockIdx.z;                 // 0..31 = br*16 + (b*4+h)
    int brx = z >> 4, zz = z & 15;
    int b = zz >> 2, h = zz & 3;
    const float* Qp = Q + (long)brx * QSZ_ + (long)b * 1024 * 128 + h * 32;
    const float* Kp = Kt + (long)brx * QSZ_ + (long)b * 1024 * 128 + h * 32;
    int i0 = blockIdx.y * 64, j0 = blockIdx.x * 64;
    int tid = threadIdx.x;
    #pragma unroll
    for (int l = 0; l < 8; l++) {
        int e = tid + l * 256;
        int r = e >> 5, c = e & 31;
        Qs[r][c] = Qp[(long)(i0 + r) * 128 + c];
        KsT[c][r] = Kp[(long)(j0 + r) * 128 + c];
    }
    __syncthreads();
    int ty = tid >> 4, tx = tid & 15;
    ull acc2[4][2];
    #pragma unroll
    for (int i = 0; i < 4; i++) { acc2[i][0] = 0ull; acc2[i][1] = 0ull; }
    #pragma unroll
    for (int d = 0; d < 32; d++) {
        const ull* bp = (const ull*)&KsT[d][tx * 4];
        ull b0 = bp[0], b1 = bp[1];
        #pragma unroll
        for (int i = 0; i < 4; i++) {
            float a = Qs[ty * 4 + i][d];
            ull a2 = pk2(a, a);
            FMA2_(acc2[i][0], a2, b0);
            FMA2_(acc2[i][1], a2, b1);
        }
    }
    const float scale = 0.17677669529663687f;
    float sc[4][4];
    #pragma unroll
    for (int i = 0; i < 4; i++) {
        upk2(acc2[i][0], sc[i][0], sc[i][1]);
        upk2(acc2[i][1], sc[i][2], sc[i][3]);
        float m = -3.4e38f;
        #pragma unroll
        for (int j = 0; j < 4; j++) { sc[i][j] *= scale; m = fmaxf(m, sc[i][j]); }
        // vectorized store of the 4 contiguous cols
        *(float4*)&S[((long)z * 1024 + i0 + ty * 4 + i) * 1024 + j0 + tx * 4] =
            make_float4(sc[i][0], sc[i][1], sc[i][2], sc[i][3]);
        rmaxS[ty * 4 + i][tx] = m;
    }
    __syncthreads();
    if (tid < 64) {
        float m = rmaxS[tid][0];
        #pragma unroll
        for (int q = 1; q < 16; q++) m = fmaxf(m, rmaxS[tid][q]);
        rmaxS[tid][16] = m;
    }
    __syncthreads();
    #pragma unroll
    for (int i = 0; i < 4; i++) {
        float m = rmaxS[ty * 4 + i][16];
        float p = 0.f;
        #pragma unroll
        for (int j = 0; j < 4; j++) p += __expf(sc[i][j] - m);
        rsumS[ty * 4 + i][tx] = p;
    }
    __syncthreads();
    if (tid < 64) {
        float s = 0.f;
        #pragma unroll
        for (int q = 0; q < 16; q++) s += rsumS[tid][q];
        long ridx = ((long)z * 1024 + i0 + tid) * 16 + blockIdx.x;
        pmax[ridx] = rmaxS[tid][16];
        psum[ridx] = s;
    }
}

// ---------------- attention: combine split-softmax partials per row ----------------
__global__ void attn_reduce_kernel(const float* __restrict__ pmax,
                                   const float* __restrict__ psum,
                                   float* __restrict__ gmax, float* __restrict__ gsum) {
    int r = blockIdx.x * 256 + threadIdx.x;     // 0..32767
    const float* pm = pmax + (long)r * 16;
    const float* ps = psum + (long)r * 16;
    float m = pm[0];
    #pragma unroll
    for (int q = 1; q < 16; q++) m = fmaxf(m, pm[q]);
    float s = 0.f;
    #pragma unroll
    for (int q = 0; q < 16; q++) s += ps[q] * __expf(pm[q] - m);
    gmax[r] = m;
    gsum[r] = s;
}

// ---------------- attention: apply (exp on load, FMA2, normalize at end) ----------------
__global__ void __launch_bounds__(256) attn_apply_kernel(
        const float* __restrict__ S, const float* __restrict__ V,
        const float* __restrict__ gmax, const float* __restrict__ gsum,
        float* __restrict__ O) {
    __shared__ __align__(16) float Ps[64][66];
    __shared__ __align__(16) float Vs[64][34];
    __shared__ float gmr[64], gsr[64];
    int z = blockIdx.y;                 // 0..31
    int brx = z >> 4, zz = z & 15;
    int b = zz >> 2, h = zz & 3;
    int i0 = blockIdx.x * 64;
    int tid = threadIdx.x;
    int ty = tid >> 4, tx = tid & 15;
    const float* Vp = V + (long)brx * QSZ_;
    float* Op = O + (long)brx * QSZ_;
    if (tid < 64) {
        gmr[tid] = gmax[(long)z * 1024 + i0 + tid];
        gsr[tid] = gsum[(long)z * 1024 + i0 + tid];
    }
    __syncthreads();
    ull acc2[4];
    #pragma unroll
    for (int i = 0; i < 4; i++) acc2[i] = 0ull;
    for (int j0 = 0; j0 < 1024; j0 += 64) {
        #pragma unroll
        for (int l = 0; l < 16; l++) {
            int e = tid + l * 256;
            int r = e >> 6, c = e & 63;
            float s = S[((long)z * 1024 + i0 + r) * 1024 + j0 + c];
            Ps[r][c] = __expf(s - gmr[r]);
        }
        #pragma unroll
        for (int l = 0; l < 8; l++) {
            int e = tid + l * 256;
            int r = e >> 5, c = e & 31;
            Vs[r][c] = Vp[(long)(b * 1024 + j0 + r) * 128 + h * 32 + c];
        }
        __syncthreads();
        #pragma unroll
        for (int kk = 0; kk < 64; kk++) {
            ull v2 = *(const ull*)&Vs[kk][tx * 2];
            #pragma unroll
            for (int i = 0; i < 4; i++) {
                float a = Ps[ty * 4 + i][kk];
                FMA2_(acc2[i], pk2(a, a), v2);
            }
        }
        __syncthreads();
    }
    #pragma unroll
    for (int i = 0; i < 4; i++) {
        float v0, v1;
        upk2(acc2[i], v0, v1);
        float inv = 1.0f / gsr[ty * 4 + i];
        long obase = (long)(b * 1024 + i0 + ty * 4 + i) * 128 + h * 32 + tx * 2;
        Op[obase]     = v0 * inv;
        Op[obase + 1] = v1 * inv;
    }
}

// ---------------- elementwise avg (branch-batched) ----------------
__global__ void avg_kernel(const float* __restrict__ ampV, const float* __restrict__ ampI,
                           float* __restrict__ faMap,
                           const float* __restrict__ phV, const float* __restrict__ phI,
                           float* __restrict__ fpMap) {
    int brx = blockIdx.y;
    long i = (long)blockIdx.x * 256 + threadIdx.x;
    if (brx == 0) faMap[i] = 0.5f * (ampV[i] + ampI[i]);
    else          fpMap[i] = 0.5f * (phV[i] + phI[i]);
}

// ---------------- 3x3 SAME conv: 16x16 tile, 64 co/block, channel-pair FMA2 ----------------
__global__ void __launch_bounds__(256) conv3_kernel(
        const float* __restrict__ in, const float* __restrict__ wgt,
        const float* __restrict__ bias, float* __restrict__ out,
        const float* __restrict__ resA, const float* __restrict__ resB,
        int relu) {
    __shared__ float sIn[18][18];
    __shared__ float2 sW2[32][9];
    int bz = blockIdx.z;
    int x0 = blockIdx.x * 16, y0 = blockIdx.y * 16;
    int tx = threadIdx.x & 15, ty = threadIdx.x >> 4;
    int tid = threadIdx.x;
    int x = x0 + tx, y = y0 + ty;

    ull acc[32];
    #pragma unroll
    for (int p = 0; p < 32; p++) acc[p] = 0ull;

    for (int ci = 0; ci < 64; ci++) {
        const float* ip = in + (long)(bz * 64 + ci) * 65536;
        for (int e = tid; e < 324; e += 256) {
            int ry = e / 18, rx = e % 18;
            int gy = y0 + ry - 1, gx = x0 + rx - 1;
            sIn[ry][rx] = (gy >= 0 && gy < 256 && gx >= 0 && gx < 256) ? ip[gy * 256 + gx] : 0.f;
        }
        for (int e = tid; e < 288; e += 256) {
            int p = e / 9, k = e % 9;
            sW2[p][k] = make_float2(wgt[((long)(2 * p) * 64 + ci) * 9 + k],
                                    wgt[((long)(2 * p + 1) * 64 + ci) * 9 + k]);
        }
        __syncthreads();
        ull vp[9];
        #pragma unroll
        for (int ky = 0; ky < 3; ky++)
            #pragma unroll
            for (int kx = 0; kx < 3; kx++) {
                float v = sIn[ty + ky][tx + kx];
                vp[ky * 3 + kx] = pk2(v, v);
            }
        #pragma unroll
        for (int p = 0; p < 32; p++) {
            #pragma unroll
            for (int k = 0; k < 9; k++) {
                ull w2 = *(const ull*)&sW2[p][k];
                FMA2_(acc[p], vp[k], w2);
            }
        }
        __syncthreads();
    }
    #pragma unroll
    for (int p = 0; p < 32; p++) {
        float v0, v1;
        upk2(acc[p], v0, v1);
        int co0 = 2 * p, co1 = 2 * p + 1;
        long o0 = ((long)(bz * 64 + co0) * 256 + y) * 256 + x;
        long o1 = ((long)(bz * 64 + co1) * 256 + y) * 256 + x;
        v0 += bias[co0];
        v1 += bias[co1];
        if (relu) { v0 = fmaxf(v0, 0.f); v1 = fmaxf(v1, 0.f); }
        if (resA) {
            v0 += 0.5f * (resA[o0] + resB[o0]);
            v1 += 0.5f * (resA[o1] + resB[o1]);
        }
        out[o0] = v0;
        out[o1] = v1;
    }
}

extern "C" void kernel_launch(void* const* d_in, const int* in_sizes, int n_in,
                              void* d_out, int out_size) {
    const float* vis  = (const float*)d_in[0];
    const float* ir   = (const float*)d_in[1];
    const float* bank = (const float*)d_in[2];
    const float* Wr   = (const float*)d_in[3];
    const float* br   = (const float*)d_in[4];
    const float* aW1  = (const float*)d_in[5];
    const float* ab1  = (const float*)d_in[6];
    const float* aW2  = (const float*)d_in[7];
    const float* ab2  = (const float*)d_in[8];
    const float* aWq  = (const float*)d_in[9];
    const float* aWk  = (const float*)d_in[10];
    const float* aWv  = (const float*)d_in[11];
    const float* aWo  = (const float*)d_in[12];
    const float* pW1  = (const float*)d_in[13];
    const float* pb1  = (const float*)d_in[14];
    const float* pW2  = (const float*)d_in[15];
    const float* pb2  = (const float*)d_in[16];
    const float* pWq  = (const float*)d_in[17];
    const float* pWk  = (const float*)d_in[18];
    const float* pWv  = (const float*)d_in[19];
    const float* pWo  = (const float*)d_in[20];
    const float* c1w  = (const float*)d_in[21];
    const float* c1b  = (const float*)d_in[22];
    const float* c2w  = (const float*)d_in[23];
    const float* c2b  = (const float*)d_in[24];
    float* out = (float*)d_out;

    float2* cA;
    float *ampV, *ampI, *phV, *phI, *faMap, *fpMap, *spatial, *r1;
    float *score, *selV, *selI, *q, *k, *v, *o, *att, *fs, *gm, *intent;
    float *pmax, *psum, *gmaxp, *gsump;
    int* idxp;
    cudaGetSymbolAddress((void**)&cA, g_cA);
    cudaGetSymbolAddress((void**)&ampV, g_ampV);
    cudaGetSymbolAddress((void**)&ampI, g_ampI);
    cudaGetSymbolAddress((void**)&phV, g_phV);
    cudaGetSymbolAddress((void**)&phI, g_phI);
    cudaGetSymbolAddress((void**)&faMap, g_faMap);
    cudaGetSymbolAddress((void**)&fpMap, g_fpMap);
    cudaGetSymbolAddress((void**)&spatial, g_spatial);
    cudaGetSymbolAddress((void**)&r1, g_r1);
    cudaGetSymbolAddress((void**)&score, g_scoreArr);
    cudaGetSymbolAddress((void**)&idxp, g_idxArr);
    cudaGetSymbolAddress((void**)&selV, g_selV);
    cudaGetSymbolAddress((void**)&selI, g_selI);
    cudaGetSymbolAddress((void**)&q, g_qb);
    cudaGetSymbolAddress((void**)&k, g_kb);
    cudaGetSymbolAddress((void**)&v, g_vb);
    cudaGetSymbolAddress((void**)&o, g_ob);
    cudaGetSymbolAddress((void**)&att, g_att);
    cudaGetSymbolAddress((void**)&fs, g_fs);
    cudaGetSymbolAddress((void**)&gm, g_gm);
    cudaGetSymbolAddress((void**)&intent, g_intentArr);
    cudaGetSymbolAddress((void**)&pmax, g_pmax);
    cudaGetSymbolAddress((void**)&psum, g_psum);
    cudaGetSymbolAddress((void**)&gmaxp, g_gmax);
    cudaGetSymbolAddress((void**)&gsump, g_gsum);

    twiddle_init_kernel<<<1, 256>>>();
    gap_kernel<<<512, 256>>>(vis, ir, gm);
    router_kernel<<<1, 64>>>(gm, Wr, br, bank, intent);

    const int FB = 4096;
    fft_pass2_kernel<<<FB, 256>>>(nullptr, vis, nullptr, nullptr, cA, nullptr, nullptr, nullptr, 0, +1, 1.f);
    fft_pass2_kernel<<<FB, 256>>>(cA, nullptr, nullptr, nullptr, nullptr, ampV, phV, nullptr, 1, +1, 1.f);
    fft_pass2_kernel<<<FB, 256>>>(nullptr, ir, nullptr, nullptr, cA, nullptr, nullptr, nullptr, 0, +1, 1.f);
    fft_pass2_kernel<<<FB, 256>>>(cA, nullptr, nullptr, nullptr, nullptr, ampI, phI, nullptr, 1, +1, 1.f);

    // ----- batched branch pipeline -----
    score_fused_kernel<<<dim3(256, 2), 256>>>(ampV, ampI, phV, phI, intent,
                                              aW1, ab1, aW2, ab2, pW1, pb1, pW2, pb2, score);
    topk_kernel<<<8, 1024>>>(score, idxp);
    gather_kernel<<<dim3(16384, 2), 256>>>(ampV, ampI, phV, phI, idxp, selV, selI);

    GB8 qkv;
    qkv.g[0] = { selV,          aWq, q,          nullptr };
    qkv.g[1] = { selI,          aWk, k,          nullptr };
    qkv.g[2] = { selI,          aWv, v,          nullptr };
    qkv.g[3] = { selV + SELSZ_, pWq, q + QSZ_,   nullptr };
    qkv.g[4] = { selI + SELSZ_, pWk, k + QSZ_,   nullptr };
    qkv.g[5] = { selI + SELSZ_, pWv, v + QSZ_,   nullptr };
    qkv.g[6] = { nullptr, nullptr, nullptr, nullptr };
    qkv.g[7] = { nullptr, nullptr, nullptr, nullptr };
    gemm_batched_kernel<<<dim3(1, 64, 6), 256>>>(qkv, 4096, 128, 1024);

    attn_scores_kernel<<<dim3(16, 16, 32), 256>>>(q, k, att, pmax, psum);
    attn_reduce_kernel<<<128, 256>>>(pmax, psum, gmaxp, gsump);
    attn_apply_kernel<<<dim3(16, 32), 256>>>(att, v, gmaxp, gsump, o);

    GB8 wo;
    wo.g[0] = { o,        aWo, fs,          selV };
    wo.g[1] = { o + QSZ_, pWo, fs + SELSZ_, selV + SELSZ_ };
    for (int z = 2; z < 8; z++) wo.g[z] = { nullptr, nullptr, nullptr, nullptr };
    gemm_batched_kernel<<<dim3(8, 64, 2), 256>>>(wo, 4096, 1024, 128);

    avg_kernel<<<dim3(65536, 2), 256>>>(ampV, ampI, faMap, phV, phI, fpMap);
    scatter_kernel<<<dim3(16384, 2), 256>>>(fs, idxp, faMap, fpMap);

    fft_pass2_kernel<<<FB, 256>>>(nullptr, nullptr, faMap, fpMap, cA, nullptr, nullptr, nullptr, 0, -1, 1.f);
    fft_pass2_kernel<<<FB, 256>>>(cA, nullptr, nullptr, nullptr, nullptr, nullptr, nullptr, spatial, 1, -1, 1.0f / 65536.0f);

    conv3_kernel<<<dim3(16, 16, 4), 256>>>(spatial, c1w, c1b, r1, nullptr, nullptr, 1);
    conv3_kernel<<<dim3(16, 16, 4), 256>>>(r1, c2w, c2b, out, vis, ir, 0);

    (void)in_sizes; (void)n_in; (void)out_size;
}